// round 11
// baseline (speedup 1.0000x reference)
#include <cuda_runtime.h>
#include <cuda_bf16.h>
#include <cstdint>

// Problem constants
#define BATCH 4
#define SEQ   2048
#define DMODEL 1024
#define NHEADS 16
#define HD    64
#define ROWS  (BATCH * SEQ)          // 8192
#define QKV_N (3 * DMODEL)           // 3072

// Scratch (allocation-free rule: __device__ globals)
__device__ float g_qkv[(size_t)ROWS * QKV_N];
__device__ float g_att[(size_t)ROWS * DMODEL];

// ---------------------------------------------------------------------------
// helpers
// ---------------------------------------------------------------------------
__device__ __forceinline__ uint32_t s2u(const void* p) {
    uint32_t a;
    asm("{ .reg .u64 t; cvta.to.shared.u64 t, %1; cvt.u32.u64 %0, t; }"
        : "=r"(a) : "l"(p));
    return a;
}
__device__ __forceinline__ uint32_t tf32u(float x) {
    uint32_t u; asm("cvt.rn.tf32.f32 %0, %1;" : "=r"(u) : "f"(x)); return u;
}
__device__ __forceinline__ float tf32f(float x) { return __uint_as_float(tf32u(x)); }

__device__ __forceinline__ void mma_tf32(float& d0, float& d1, float& d2, float& d3,
                                         uint32_t a0, uint32_t a1, uint32_t a2, uint32_t a3,
                                         uint32_t b0, uint32_t b1)
{
    asm volatile(
        "mma.sync.aligned.m16n8k8.row.col.f32.tf32.tf32.f32 "
        "{%0,%1,%2,%3}, {%4,%5,%6,%7}, {%8,%9}, {%0,%1,%2,%3};"
        : "+f"(d0), "+f"(d1), "+f"(d2), "+f"(d3)
        : "r"(a0), "r"(a1), "r"(a2), "r"(a3), "r"(b0), "r"(b1));
}

__device__ __forceinline__ void mma_bf16(float& d0, float& d1, float& d2, float& d3,
                                         uint32_t a0, uint32_t a1, uint32_t a2, uint32_t a3,
                                         uint32_t b0, uint32_t b1)
{
    asm volatile(
        "mma.sync.aligned.m16n8k16.row.col.f32.bf16.bf16.f32 "
        "{%0,%1,%2,%3}, {%4,%5,%6,%7}, {%8,%9}, {%0,%1,%2,%3};"
        : "+f"(d0), "+f"(d1), "+f"(d2), "+f"(d3)
        : "r"(a0), "r"(a1), "r"(a2), "r"(a3), "r"(b0), "r"(b1));
}

__device__ __forceinline__ void cpasync16(uint32_t dst, const void* src) {
    asm volatile("cp.async.cg.shared.global [%0], [%1], 16;" :: "r"(dst), "l"(src));
}
#define CP_COMMIT() asm volatile("cp.async.commit_group;" ::: "memory")
#define CP_WAIT0()  asm volatile("cp.async.wait_group 0;" ::: "memory")

// pack two floats -> bf16x2 + low-part extraction
__device__ __forceinline__ uint32_t bfpack(float a, float b) {
    __nv_bfloat162 h = __floats2bfloat162_rn(a, b);
    return *reinterpret_cast<uint32_t*>(&h);
}
__device__ __forceinline__ float bflo(uint32_t u) { return __uint_as_float(u << 16); }
__device__ __forceinline__ float bfhi(uint32_t u) { return __uint_as_float(u & 0xFFFF0000u); }

// ---------------------------------------------------------------------------
// TF32 GEMM v3: 128x128 block tile, 128 threads, 4 warps of 64x64 tiles
// (2x2 grid). 1.0 LDS per mma (vs 1.5 in v1). BK=16, register prefetch,
// cvt.rn at STS time — per-element numerics identical to v1.
// ---------------------------------------------------------------------------
#define AST 20
#define BST 136

__global__ void __launch_bounds__(128, 2) tf32_gemm_kernel(
    const float* __restrict__ A, const float* __restrict__ B,
    const float* __restrict__ bias, float* __restrict__ C,
    int M, int N, int K)
{
    __shared__ float As[128][AST];
    __shared__ float Bs[16][BST];

    const int tid  = threadIdx.x;
    const int lane = tid & 31;
    const int warp = tid >> 5;       // 0..3
    const int brow = blockIdx.y;
    const int bcol = blockIdx.x;

    // warp grid 2x2, each warp 64x64
    const int mbase = (warp >> 1) * 64;
    const int nbase = (warp & 1) * 64;
    const int r = lane >> 2;         // 0..7
    const int c = lane & 3;          // 0..3

    // loader indices
    // A: row = tid, 16 consecutive floats (4 x float4)
    // B: row = tid>>3 (0..15), col = (tid&7)*4 + 32q (4 x float4, stride 32)
    const int br = tid >> 3;
    const int bc = (tid & 7) * 4;

    const float* Ab = A + (size_t)(brow * 128 + tid) * K;
    const float* Bb = B + (size_t)br * N + bcol * 128 + bc;

    float acc[4][8][4];
    #pragma unroll
    for (int i = 0; i < 4; i++)
        #pragma unroll
        for (int j = 0; j < 8; j++)
            #pragma unroll
            for (int t = 0; t < 4; t++) acc[i][j][t] = 0.f;

    float4 pa[4], pb[4];
    #pragma unroll
    for (int q = 0; q < 4; q++) {
        pa[q] = *(const float4*)(Ab + q * 4);
        pb[q] = *(const float4*)(Bb + q * 32);
    }

    for (int k0 = 0; k0 < K; k0 += 16) {
        // store (tf32-rounded) tiles to shared
        #pragma unroll
        for (int q = 0; q < 4; q++) {
            *(float4*)&As[tid][q * 4] = make_float4(tf32f(pa[q].x), tf32f(pa[q].y),
                                                    tf32f(pa[q].z), tf32f(pa[q].w));
            *(float4*)&Bs[br][bc + q * 32] = make_float4(tf32f(pb[q].x), tf32f(pb[q].y),
                                                         tf32f(pb[q].z), tf32f(pb[q].w));
        }
        __syncthreads();

        // prefetch next chunk (overlaps compute)
        if (k0 + 16 < K) {
            #pragma unroll
            for (int q = 0; q < 4; q++) {
                pa[q] = *(const float4*)(Ab + k0 + 16 + q * 4);
                pb[q] = *(const float4*)(Bb + (size_t)(k0 + 16) * N + q * 32);
            }
        }

        #pragma unroll
        for (int ks = 0; ks < 2; ks++) {
            const int kb = ks * 8;
            uint32_t af[4][4];
            #pragma unroll
            for (int mt = 0; mt < 4; mt++) {
                const int m = mbase + mt * 16;
                af[mt][0] = __float_as_uint(As[m + r][kb + c]);
                af[mt][1] = __float_as_uint(As[m + r + 8][kb + c]);
                af[mt][2] = __float_as_uint(As[m + r][kb + c + 4]);
                af[mt][3] = __float_as_uint(As[m + r + 8][kb + c + 4]);
            }
            uint32_t bf[8][2];
            #pragma unroll
            for (int nt = 0; nt < 8; nt++) {
                const int n = nbase + nt * 8 + r;
                bf[nt][0] = __float_as_uint(Bs[kb + c][n]);
                bf[nt][1] = __float_as_uint(Bs[kb + c + 4][n]);
            }
            #pragma unroll
            for (int mt = 0; mt < 4; mt++)
                #pragma unroll
                for (int nt = 0; nt < 8; nt++)
                    mma_tf32(acc[mt][nt][0], acc[mt][nt][1],
                             acc[mt][nt][2], acc[mt][nt][3],
                             af[mt][0], af[mt][1], af[mt][2], af[mt][3],
                             bf[nt][0], bf[nt][1]);
        }
        __syncthreads();
    }

    #pragma unroll
    for (int mt = 0; mt < 4; mt++) {
        const int row0 = brow * 128 + mbase + mt * 16 + r;
        #pragma unroll
        for (int nt = 0; nt < 8; nt++) {
            const int col = bcol * 128 + nbase + nt * 8 + 2 * c;
            float2 v0 = make_float2(acc[mt][nt][0], acc[mt][nt][1]);
            float2 v1 = make_float2(acc[mt][nt][2], acc[mt][nt][3]);
            if (bias) {
                float2 bb = *(const float2*)(bias + col);
                v0.x += bb.x; v0.y += bb.y;
                v1.x += bb.x; v1.y += bb.y;
            }
            *(float2*)(C + (size_t)row0 * N + col)       = v0;
            *(float2*)(C + (size_t)(row0 + 8) * N + col) = v1;
        }
    }
}

// ---------------------------------------------------------------------------
// Flash attention v4 (round-9 winner, byte-identical): bf16 3-split S,
// tf32 PV, shuffle P relayout, K split in loader, single-buffered.
// smem 73728 B -> 2 CTAs/SM.
// ---------------------------------------------------------------------------
#define FBM 128
#define FBN 64
#define QBST 36
#define KBST 36
#define VST 72
#define FLASH_SMEM ((2*FBM*QBST + 2*FBN*KBST + FBN*VST) * 4)   // 73728 B

__global__ void __launch_bounds__(256, 2) flash_tc_kernel(
    const float* __restrict__ qkv, float* __restrict__ out)
{
    extern __shared__ uint32_t smf[];
    uint32_t* Qh = smf;
    uint32_t* Ql = Qh + FBM * QBST;
    uint32_t* Kh = Ql + FBM * QBST;
    uint32_t* Kl = Kh + FBN * KBST;
    float*    Vs = (float*)(Kl + FBN * KBST);

    const int tid  = threadIdx.x;
    const int lane = tid & 31;
    const int warp = tid >> 5;
    const int qt = (int)gridDim.x - 1 - (int)blockIdx.x;   // big blocks first
    const int bh = blockIdx.y;
    const int b  = bh >> 4;
    const int h  = bh & 15;

    const size_t rs = (size_t)QKV_N;
    const float* qb = qkv + (size_t)b * SEQ * rs + h * HD;
    const float* kb = qb + DMODEL;
    const int q0 = qt * FBM;

    for (int idx = tid; idx < FBM * 32; idx += 256) {
        const int row = idx >> 5, j = idx & 31;
        float2 q = *(const float2*)(qb + (size_t)(q0 + row) * rs + 2 * j);
        uint32_t hu = bfpack(q.x, q.y);
        Qh[row * QBST + j] = hu;
        Ql[row * QBST + j] = bfpack(q.x - bflo(hu), q.y - bfhi(hu));
    }

    const int r = lane >> 2;
    const int c = lane & 3;
    const int m0 = warp * 16;

    float o[8][4];
    #pragma unroll
    for (int nt = 0; nt < 8; nt++)
        #pragma unroll
        for (int t = 0; t < 4; t++) o[nt][t] = 0.f;
    float mx0 = -1e30f, mx1 = -1e30f, l0 = 0.f, l1 = 0.f;
    const float sl2e = 0.125f * 1.4426950408889634f;

    const int nkt = 2 * qt + 2;
    for (int kt = 0; kt < nkt; kt++) {
        __syncthreads();

        for (int idx = tid; idx < FBN * 16; idx += 256) {
            int rr = idx >> 4, ch = (idx & 15) * 4;
            cpasync16(s2u(&Vs[rr * VST + ch]),
                      kb + (size_t)(kt * FBN + rr) * rs + DMODEL + ch);
        }
        CP_COMMIT();
        for (int idx = tid; idx < FBN * 32; idx += 256) {
            const int row = idx >> 5, j = idx & 31;
            float2 kv = *(const float2*)(kb + (size_t)(kt * FBN + row) * rs + 2 * j);
            uint32_t hu = bfpack(kv.x, kv.y);
            Kh[row * KBST + j] = hu;
            Kl[row * KBST + j] = bfpack(kv.x - bflo(hu), kv.y - bfhi(hu));
        }
        CP_WAIT0();
        __syncthreads();

        float s[8][4];
        #pragma unroll
        for (int nt = 0; nt < 8; nt++)
            #pragma unroll
            for (int t = 0; t < 4; t++) s[nt][t] = 0.f;

        #pragma unroll
        for (int g = 0; g < 4; g++) {
            const int qo = 8 * g + c;
            uint32_t ah0 = Qh[(m0 + r) * QBST + qo];
            uint32_t ah1 = Qh[(m0 + r + 8) * QBST + qo];
            uint32_t ah2 = Qh[(m0 + r) * QBST + qo + 4];
            uint32_t ah3 = Qh[(m0 + r + 8) * QBST + qo + 4];
            uint32_t al0 = Ql[(m0 + r) * QBST + qo];
            uint32_t al1 = Ql[(m0 + r + 8) * QBST + qo];
            uint32_t al2 = Ql[(m0 + r) * QBST + qo + 4];
            uint32_t al3 = Ql[(m0 + r + 8) * QBST + qo + 4];
            #pragma unroll
            for (int half = 0; half < 2; half++) {
                uint32_t bhf[4][2], blf[4][2];
                #pragma unroll
                for (int q2 = 0; q2 < 4; q2++) {
                    const int n = (half * 4 + q2) * 8 + r;
                    bhf[q2][0] = Kh[n * KBST + qo];
                    bhf[q2][1] = Kh[n * KBST + qo + 4];
                    blf[q2][0] = Kl[n * KBST + qo];
                    blf[q2][1] = Kl[n * KBST + qo + 4];
                }
                #pragma unroll
                for (int q2 = 0; q2 < 4; q2++) {
                    const int nt = half * 4 + q2;
                    mma_bf16(s[nt][0], s[nt][1], s[nt][2], s[nt][3],
                             ah0, ah1, ah2, ah3, bhf[q2][0], bhf[q2][1]);
                }
                #pragma unroll
                for (int q2 = 0; q2 < 4; q2++) {
                    const int nt = half * 4 + q2;
                    mma_bf16(s[nt][0], s[nt][1], s[nt][2], s[nt][3],
                             ah0, ah1, ah2, ah3, blf[q2][0], blf[q2][1]);
                }
                #pragma unroll
                for (int q2 = 0; q2 < 4; q2++) {
                    const int nt = half * 4 + q2;
                    mma_bf16(s[nt][0], s[nt][1], s[nt][2], s[nt][3],
                             al0, al1, al2, al3, bhf[q2][0], bhf[q2][1]);
                }
            }
        }

        if (kt >= 2 * qt) {
            const int q0i = q0 + m0 + r;
            #pragma unroll
            for (int nt = 0; nt < 8; nt++) {
                int k0i = kt * FBN + nt * 8 + 2 * c;
                if (k0i     > q0i)     s[nt][0] = -1e30f;
                if (k0i + 1 > q0i)     s[nt][1] = -1e30f;
                if (k0i     > q0i + 8) s[nt][2] = -1e30f;
                if (k0i + 1 > q0i + 8) s[nt][3] = -1e30f;
            }
        }

        {
            float t = -1e30f;
            #pragma unroll
            for (int nt = 0; nt < 8; nt++) t = fmaxf(t, fmaxf(s[nt][0], s[nt][1]));
            t = fmaxf(t, __shfl_xor_sync(0xffffffffu, t, 1));
            t = fmaxf(t, __shfl_xor_sync(0xffffffffu, t, 2));
            t *= sl2e;
            float mn = fmaxf(mx0, t);
            float alpha = exp2f(mx0 - mn);
            float ps = 0.f;
            #pragma unroll
            for (int nt = 0; nt < 8; nt++) {
                float p0 = exp2f(s[nt][0] * sl2e - mn);
                float p1 = exp2f(s[nt][1] * sl2e - mn);
                s[nt][0] = p0; s[nt][1] = p1; ps += p0 + p1;
            }
            ps += __shfl_xor_sync(0xffffffffu, ps, 1);
            ps += __shfl_xor_sync(0xffffffffu, ps, 2);
            l0 = l0 * alpha + ps; mx0 = mn;
            #pragma unroll
            for (int nt = 0; nt < 8; nt++) { o[nt][0] *= alpha; o[nt][1] *= alpha; }
        }
        {
            float t = -1e30f;
            #pragma unroll
            for (int nt = 0; nt < 8; nt++) t = fmaxf(t, fmaxf(s[nt][2], s[nt][3]));
            t = fmaxf(t, __shfl_xor_sync(0xffffffffu, t, 1));
            t = fmaxf(t, __shfl_xor_sync(0xffffffffu, t, 2));
            t *= sl2e;
            float mn = fmaxf(mx1, t);
            float alpha = exp2f(mx1 - mn);
            float ps = 0.f;
            #pragma unroll
            for (int nt = 0; nt < 8; nt++) {
                float p0 = exp2f(s[nt][2] * sl2e - mn);
                float p1 = exp2f(s[nt][3] * sl2e - mn);
                s[nt][2] = p0; s[nt][3] = p1; ps += p0 + p1;
            }
            ps += __shfl_xor_sync(0xffffffffu, ps, 1);
            ps += __shfl_xor_sync(0xffffffffu, ps, 2);
            l1 = l1 * alpha + ps; mx1 = mn;
            #pragma unroll
            for (int nt = 0; nt < 8; nt++) { o[nt][2] *= alpha; o[nt][3] *= alpha; }
        }

        {
            const int src0 = 4 * r + (c >> 1);
            const int src1 = src0 + 2;
            const bool odd = (c & 1);
            #pragma unroll
            for (int kc = 0; kc < 8; kc++) {
                const int k8 = kc * 8;
                float t00 = __shfl_sync(0xffffffffu, s[kc][0], src0);
                float t01 = __shfl_sync(0xffffffffu, s[kc][1], src0);
                float t02 = __shfl_sync(0xffffffffu, s[kc][2], src0);
                float t03 = __shfl_sync(0xffffffffu, s[kc][3], src0);
                float t10 = __shfl_sync(0xffffffffu, s[kc][0], src1);
                float t11 = __shfl_sync(0xffffffffu, s[kc][1], src1);
                float t12 = __shfl_sync(0xffffffffu, s[kc][2], src1);
                float t13 = __shfl_sync(0xffffffffu, s[kc][3], src1);
                uint32_t a0 = tf32u(odd ? t01 : t00);
                uint32_t a1 = tf32u(odd ? t03 : t02);
                uint32_t a2 = tf32u(odd ? t11 : t10);
                uint32_t a3 = tf32u(odd ? t13 : t12);
                #pragma unroll
                for (int nt = 0; nt < 8; nt++) {
                    uint32_t b0 = tf32u(Vs[(k8 + c) * VST + nt * 8 + r]);
                    uint32_t b1 = tf32u(Vs[(k8 + c + 4) * VST + nt * 8 + r]);
                    mma_tf32(o[nt][0], o[nt][1], o[nt][2], o[nt][3], a0, a1, a2, a3, b0, b1);
                }
            }
        }
    }

    const float inv0 = 1.f / l0;
    const float inv1 = 1.f / l1;
    const size_t row0 = (size_t)(b * SEQ + q0 + m0 + r) * DMODEL + h * HD;
    const size_t row1 = row0 + (size_t)8 * DMODEL;
    #pragma unroll
    for (int nt = 0; nt < 8; nt++) {
        const int col = nt * 8 + 2 * c;
        *(float2*)(out + row0 + col) = make_float2(o[nt][0] * inv0, o[nt][1] * inv0);
        *(float2*)(out + row1 + col) = make_float2(o[nt][2] * inv1, o[nt][3] * inv1);
    }
}

// ---------------------------------------------------------------------------
extern "C" void kernel_launch(void* const* d_in, const int* in_sizes, int n_in,
                              void* d_out, int out_size)
{
    const float* x     = (const float*)d_in[0];
    const float* w_qkv = (const float*)d_in[1];
    const float* w_out = (const float*)d_in[2];
    const float* b_out = (const float*)d_in[3];
    float* out = (float*)d_out;

    float *qkv, *att;
    cudaGetSymbolAddress((void**)&qkv, g_qkv);
    cudaGetSymbolAddress((void**)&att, g_att);

    // 1) QKV projection (tf32 mma v3: 64x64 warp tiles, 128 threads)
    {
        dim3 grid(QKV_N / 128, ROWS / 128);
        tf32_gemm_kernel<<<grid, 128>>>(x, w_qkv, nullptr, qkv, ROWS, QKV_N, DMODEL);
    }

    // 2) Flash attention v4 (round-9 config)
    {
        cudaFuncSetAttribute(flash_tc_kernel,
                             cudaFuncAttributeMaxDynamicSharedMemorySize, FLASH_SMEM);
        dim3 grid(SEQ / FBM, BATCH * NHEADS);
        flash_tc_kernel<<<grid, 256, FLASH_SMEM>>>(qkv, att);
    }

    // 3) Output projection + bias
    {
        dim3 grid(DMODEL / 128, ROWS / 128);
        tf32_gemm_kernel<<<grid, 128>>>(att, w_out, b_out, out, ROWS, DMODEL, DMODEL);
    }
}

// round 12
// speedup vs baseline: 1.3575x; 1.3575x over previous
#include <cuda_runtime.h>
#include <cuda_bf16.h>
#include <cuda_fp16.h>
#include <cstdint>

// Problem constants
#define BATCH 4
#define SEQ   2048
#define DMODEL 1024
#define NHEADS 16
#define HD    64
#define ROWS  (BATCH * SEQ)          // 8192
#define QKV_N (3 * DMODEL)           // 3072

// Scratch (allocation-free rule: __device__ globals)
__device__ float g_qkv[(size_t)ROWS * QKV_N];
__device__ float g_att[(size_t)ROWS * DMODEL];

// ---------------------------------------------------------------------------
// helpers
// ---------------------------------------------------------------------------
__device__ __forceinline__ uint32_t tf32u(float x) {
    uint32_t u; asm("cvt.rn.tf32.f32 %0, %1;" : "=r"(u) : "f"(x)); return u;
}
__device__ __forceinline__ float tf32f(float x) { return __uint_as_float(tf32u(x)); }

__device__ __forceinline__ void mma_tf32(float& d0, float& d1, float& d2, float& d3,
                                         uint32_t a0, uint32_t a1, uint32_t a2, uint32_t a3,
                                         uint32_t b0, uint32_t b1)
{
    asm volatile(
        "mma.sync.aligned.m16n8k8.row.col.f32.tf32.tf32.f32 "
        "{%0,%1,%2,%3}, {%4,%5,%6,%7}, {%8,%9}, {%0,%1,%2,%3};"
        : "+f"(d0), "+f"(d1), "+f"(d2), "+f"(d3)
        : "r"(a0), "r"(a1), "r"(a2), "r"(a3), "r"(b0), "r"(b1));
}

__device__ __forceinline__ void mma_f16(float& d0, float& d1, float& d2, float& d3,
                                        uint32_t a0, uint32_t a1, uint32_t a2, uint32_t a3,
                                        uint32_t b0, uint32_t b1)
{
    asm volatile(
        "mma.sync.aligned.m16n8k16.row.col.f32.f16.f16.f32 "
        "{%0,%1,%2,%3}, {%4,%5,%6,%7}, {%8,%9}, {%0,%1,%2,%3};"
        : "+f"(d0), "+f"(d1), "+f"(d2), "+f"(d3)
        : "r"(a0), "r"(a1), "r"(a2), "r"(a3), "r"(b0), "r"(b1));
}

// pack two floats -> f16x2 (lo = a, hi = b)
__device__ __forceinline__ uint32_t h2pack(float a, float b) {
    __half2 h = __floats2half2_rn(a, b);
    return *reinterpret_cast<uint32_t*>(&h);
}

// ---------------------------------------------------------------------------
// TF32 GEMM — exact round-2 kernel (419us QKV, proven; do not touch)
// ---------------------------------------------------------------------------
#define BM 128
#define BN 128
#define BKK 16
#define AST 20
#define BST 136

__global__ void __launch_bounds__(256, 2) tf32_gemm_kernel(
    const float* __restrict__ A, const float* __restrict__ B,
    const float* __restrict__ bias, float* __restrict__ C,
    int M, int N, int K)
{
    __shared__ float As[BM][AST];
    __shared__ float Bs[BKK][BST];

    const int tid  = threadIdx.x;
    const int lane = tid & 31;
    const int warp = tid >> 5;
    const int brow = blockIdx.y;
    const int bcol = blockIdx.x;

    const int am0 = tid >> 2;
    const int aq  = (tid & 3) * 4;
    const int bk0 = tid >> 5;
    const int bn0 = (tid & 31) * 4;

    const int wrow = warp >> 2;
    const int wcol = warp & 3;
    const int mbase = wrow * 64;
    const int nbase = wcol * 32;
    const int r = lane >> 2;
    const int c = lane & 3;

    const float* Ab = A + (size_t)brow * BM * K;
    const float* Bb = B + (size_t)bcol * BN;

    float acc[4][4][4];
    #pragma unroll
    for (int i = 0; i < 4; i++)
        #pragma unroll
        for (int j = 0; j < 4; j++)
            #pragma unroll
            for (int t = 0; t < 4; t++) acc[i][j][t] = 0.f;

    float4 pa0 = *(const float4*)(Ab + (size_t)am0 * K + aq);
    float4 pa1 = *(const float4*)(Ab + (size_t)(am0 + 64) * K + aq);
    float4 pb0 = *(const float4*)(Bb + (size_t)bk0 * N + bn0);
    float4 pb1 = *(const float4*)(Bb + (size_t)(bk0 + 8) * N + bn0);

    for (int k0 = 0; k0 < K; k0 += BKK) {
        *(float4*)&As[am0][aq] = make_float4(tf32f(pa0.x), tf32f(pa0.y), tf32f(pa0.z), tf32f(pa0.w));
        *(float4*)&As[am0 + 64][aq] = make_float4(tf32f(pa1.x), tf32f(pa1.y), tf32f(pa1.z), tf32f(pa1.w));
        *(float4*)&Bs[bk0][bn0] = make_float4(tf32f(pb0.x), tf32f(pb0.y), tf32f(pb0.z), tf32f(pb0.w));
        *(float4*)&Bs[bk0 + 8][bn0] = make_float4(tf32f(pb1.x), tf32f(pb1.y), tf32f(pb1.z), tf32f(pb1.w));
        __syncthreads();

        if (k0 + BKK < K) {
            pa0 = *(const float4*)(Ab + (size_t)am0 * K + k0 + BKK + aq);
            pa1 = *(const float4*)(Ab + (size_t)(am0 + 64) * K + k0 + BKK + aq);
            pb0 = *(const float4*)(Bb + (size_t)(k0 + BKK + bk0) * N + bn0);
            pb1 = *(const float4*)(Bb + (size_t)(k0 + BKK + bk0 + 8) * N + bn0);
        }

        #pragma unroll
        for (int ks = 0; ks < 2; ks++) {
            const int kb = ks * 8;
            uint32_t af[4][4];
            #pragma unroll
            for (int mt = 0; mt < 4; mt++) {
                const int m = mbase + mt * 16;
                af[mt][0] = __float_as_uint(As[m + r][kb + c]);
                af[mt][1] = __float_as_uint(As[m + r + 8][kb + c]);
                af[mt][2] = __float_as_uint(As[m + r][kb + c + 4]);
                af[mt][3] = __float_as_uint(As[m + r + 8][kb + c + 4]);
            }
            uint32_t bf[4][2];
            #pragma unroll
            for (int nt = 0; nt < 4; nt++) {
                const int n = nbase + nt * 8 + r;
                bf[nt][0] = __float_as_uint(Bs[kb + c][n]);
                bf[nt][1] = __float_as_uint(Bs[kb + c + 4][n]);
            }
            #pragma unroll
            for (int mt = 0; mt < 4; mt++)
                #pragma unroll
                for (int nt = 0; nt < 4; nt++)
                    mma_tf32(acc[mt][nt][0], acc[mt][nt][1],
                             acc[mt][nt][2], acc[mt][nt][3],
                             af[mt][0], af[mt][1], af[mt][2], af[mt][3],
                             bf[nt][0], bf[nt][1]);
        }
        __syncthreads();
    }

    #pragma unroll
    for (int mt = 0; mt < 4; mt++) {
        const int row0 = brow * BM + mbase + mt * 16 + r;
        #pragma unroll
        for (int nt = 0; nt < 4; nt++) {
            const int col = bcol * BN + nbase + nt * 8 + 2 * c;
            float2 v0 = make_float2(acc[mt][nt][0], acc[mt][nt][1]);
            float2 v1 = make_float2(acc[mt][nt][2], acc[mt][nt][3]);
            if (bias) {
                float2 bb = *(const float2*)(bias + col);
                v0.x += bb.x; v0.y += bb.y;
                v1.x += bb.x; v1.y += bb.y;
            }
            *(float2*)(C + (size_t)row0 * N + col)       = v0;
            *(float2*)(C + (size_t)(row0 + 8) * N + col) = v1;
        }
    }
}

// ---------------------------------------------------------------------------
// Flash attention v6 (fp16 single-precision mma), causal.
// S = Q@K^T via mma.m16n8k16.f16 (1 instr/k16); PV likewise. The S C-frag
// maps in-lane onto the PV A-frag -> zero shuffles, zero P smem.
// Q/K packed f16x2 along d (stride 36 u32: banks 4r+c, conflict-free);
// V packed f16x2 along k-pairs (stride 72: banks 8c+r, conflict-free).
// smem 36864 B -> 2 CTAs/SM.
// ---------------------------------------------------------------------------
#define FBM 128
#define FBN 64
#define QPST 36   // Qp row stride (u32)
#define KPST 36   // Kp row stride (u32)
#define VPST 72   // Vp row stride (u32), rows are k2-pairs
#define FLASH_SMEM ((FBM*QPST + FBN*KPST + 32*VPST) * 4)   // 36864 B

__global__ void __launch_bounds__(256, 2) flash_tc_kernel(
    const float* __restrict__ qkv, float* __restrict__ out)
{
    extern __shared__ uint32_t smf[];
    uint32_t* Qp = smf;                       // [128][QPST] f16x2 pairs along d
    uint32_t* Kp = Qp + FBM * QPST;           // [64][KPST]
    uint32_t* Vp = Kp + FBN * KPST;           // [32 k2][VPST] pairs across keys

    const int tid  = threadIdx.x;
    const int lane = tid & 31;
    const int warp = tid >> 5;
    const int qt = (int)gridDim.x - 1 - (int)blockIdx.x;   // big blocks first
    const int bh = blockIdx.y;
    const int b  = bh >> 4;
    const int h  = bh & 15;

    const size_t rs = (size_t)QKV_N;
    const float* qb = qkv + (size_t)b * SEQ * rs + h * HD;
    const float* kb = qb + DMODEL;
    const float* vb = qb + 2 * DMODEL;
    const int q0 = qt * FBM;

    // ---- Q prologue: fp32 -> f16x2 packed pairs along d ----
    for (int idx = tid; idx < FBM * 32; idx += 256) {
        const int row = idx >> 5, j = idx & 31;
        float2 q = *(const float2*)(qb + (size_t)(q0 + row) * rs + 2 * j);
        Qp[row * QPST + j] = h2pack(q.x, q.y);
    }

    const int r = lane >> 2;       // 0..7
    const int c = lane & 3;        // 0..3
    const int m0 = warp * 16;

    float o[8][4];
    #pragma unroll
    for (int nt = 0; nt < 8; nt++)
        #pragma unroll
        for (int t = 0; t < 4; t++) o[nt][t] = 0.f;
    float mx0 = -1e30f, mx1 = -1e30f, l0 = 0.f, l1 = 0.f;
    const float sl2e = 0.125f * 1.4426950408889634f;

    const int nkt = 2 * qt + 2;
    for (int kt = 0; kt < nkt; kt++) {
        __syncthreads();   // previous iter's readers done (covers Q stores iter 0)

        // K tile: pack f16x2 pairs along d
        for (int idx = tid; idx < FBN * 32; idx += 256) {
            const int row = idx >> 5, j = idx & 31;
            float2 kv = *(const float2*)(kb + (size_t)(kt * FBN + row) * rs + 2 * j);
            Kp[row * KPST + j] = h2pack(kv.x, kv.y);
        }
        // V tile: pack f16x2 pairs across adjacent key rows
        for (int idx = tid; idx < 32 * 16; idx += 256) {
            const int k2 = idx >> 4, j4 = (idx & 15) * 4;
            const float* v0p = vb + (size_t)(kt * FBN + 2 * k2) * rs + j4;
            float4 a = *(const float4*)v0p;
            float4 d = *(const float4*)(v0p + rs);
            Vp[k2 * VPST + j4 + 0] = h2pack(a.x, d.x);
            Vp[k2 * VPST + j4 + 1] = h2pack(a.y, d.y);
            Vp[k2 * VPST + j4 + 2] = h2pack(a.z, d.z);
            Vp[k2 * VPST + j4 + 3] = h2pack(a.w, d.w);
        }
        __syncthreads();

        // ---- S = Q @ K^T : fp16 single, 1 mma per (g, nt) ----
        float s[8][4];
        #pragma unroll
        for (int nt = 0; nt < 8; nt++)
            #pragma unroll
            for (int t = 0; t < 4; t++) s[nt][t] = 0.f;

        #pragma unroll
        for (int g = 0; g < 4; g++) {
            const int qo = 8 * g + c;
            uint32_t a0 = Qp[(m0 + r) * QPST + qo];
            uint32_t a1 = Qp[(m0 + r + 8) * QPST + qo];
            uint32_t a2 = Qp[(m0 + r) * QPST + qo + 4];
            uint32_t a3 = Qp[(m0 + r + 8) * QPST + qo + 4];
            #pragma unroll
            for (int nt = 0; nt < 8; nt++) {
                const int n = nt * 8 + r;
                uint32_t b0 = Kp[n * KPST + qo];
                uint32_t b1 = Kp[n * KPST + qo + 4];
                mma_f16(s[nt][0], s[nt][1], s[nt][2], s[nt][3], a0, a1, a2, a3, b0, b1);
            }
        }

        // ---- causal mask ----
        if (kt >= 2 * qt) {
            const int q0i = q0 + m0 + r;
            #pragma unroll
            for (int nt = 0; nt < 8; nt++) {
                int k0i = kt * FBN + nt * 8 + 2 * c;
                if (k0i     > q0i)     s[nt][0] = -1e30f;
                if (k0i + 1 > q0i)     s[nt][1] = -1e30f;
                if (k0i     > q0i + 8) s[nt][2] = -1e30f;
                if (k0i + 1 > q0i + 8) s[nt][3] = -1e30f;
            }
        }

        // ---- online softmax: row r (frags 0,1) ----
        {
            float t = -1e30f;
            #pragma unroll
            for (int nt = 0; nt < 8; nt++) t = fmaxf(t, fmaxf(s[nt][0], s[nt][1]));
            t = fmaxf(t, __shfl_xor_sync(0xffffffffu, t, 1));
            t = fmaxf(t, __shfl_xor_sync(0xffffffffu, t, 2));
            t *= sl2e;
            float mn = fmaxf(mx0, t);
            float alpha = exp2f(mx0 - mn);
            float ps = 0.f;
            #pragma unroll
            for (int nt = 0; nt < 8; nt++) {
                float p0 = exp2f(s[nt][0] * sl2e - mn);
                float p1 = exp2f(s[nt][1] * sl2e - mn);
                s[nt][0] = p0; s[nt][1] = p1; ps += p0 + p1;
            }
            ps += __shfl_xor_sync(0xffffffffu, ps, 1);
            ps += __shfl_xor_sync(0xffffffffu, ps, 2);
            l0 = l0 * alpha + ps; mx0 = mn;
            #pragma unroll
            for (int nt = 0; nt < 8; nt++) { o[nt][0] *= alpha; o[nt][1] *= alpha; }
        }
        // ---- row r+8 (frags 2,3) ----
        {
            float t = -1e30f;
            #pragma unroll
            for (int nt = 0; nt < 8; nt++) t = fmaxf(t, fmaxf(s[nt][2], s[nt][3]));
            t = fmaxf(t, __shfl_xor_sync(0xffffffffu, t, 1));
            t = fmaxf(t, __shfl_xor_sync(0xffffffffu, t, 2));
            t *= sl2e;
            float mn = fmaxf(mx1, t);
            float alpha = exp2f(mx1 - mn);
            float ps = 0.f;
            #pragma unroll
            for (int nt = 0; nt < 8; nt++) {
                float p0 = exp2f(s[nt][2] * sl2e - mn);
                float p1 = exp2f(s[nt][3] * sl2e - mn);
                s[nt][2] = p0; s[nt][3] = p1; ps += p0 + p1;
            }
            ps += __shfl_xor_sync(0xffffffffu, ps, 1);
            ps += __shfl_xor_sync(0xffffffffu, ps, 2);
            l1 = l1 * alpha + ps; mx1 = mn;
            #pragma unroll
            for (int nt = 0; nt < 8; nt++) { o[nt][2] *= alpha; o[nt][3] *= alpha; }
        }

        // ---- O += P @ V : fp16, S C-frag -> A-frag in-lane (no shuffles) ----
        #pragma unroll
        for (int kk = 0; kk < 4; kk++) {
            uint32_t a0 = h2pack(s[2 * kk][0],     s[2 * kk][1]);
            uint32_t a1 = h2pack(s[2 * kk][2],     s[2 * kk][3]);
            uint32_t a2 = h2pack(s[2 * kk + 1][0], s[2 * kk + 1][1]);
            uint32_t a3 = h2pack(s[2 * kk + 1][2], s[2 * kk + 1][3]);
            #pragma unroll
            for (int nt = 0; nt < 8; nt++) {
                const int n = nt * 8 + r;
                uint32_t b0 = Vp[(8 * kk + c) * VPST + n];
                uint32_t b1 = Vp[(8 * kk + c + 4) * VPST + n];
                mma_f16(o[nt][0], o[nt][1], o[nt][2], o[nt][3], a0, a1, a2, a3, b0, b1);
            }
        }
    }

    // ---- epilogue ----
    const float inv0 = 1.f / l0;
    const float inv1 = 1.f / l1;
    const size_t row0 = (size_t)(b * SEQ + q0 + m0 + r) * DMODEL + h * HD;
    const size_t row1 = row0 + (size_t)8 * DMODEL;
    #pragma unroll
    for (int nt = 0; nt < 8; nt++) {
        const int col = nt * 8 + 2 * c;
        *(float2*)(out + row0 + col) = make_float2(o[nt][0] * inv0, o[nt][1] * inv0);
        *(float2*)(out + row1 + col) = make_float2(o[nt][2] * inv1, o[nt][3] * inv1);
    }
}

// ---------------------------------------------------------------------------
extern "C" void kernel_launch(void* const* d_in, const int* in_sizes, int n_in,
                              void* d_out, int out_size)
{
    const float* x     = (const float*)d_in[0];
    const float* w_qkv = (const float*)d_in[1];
    const float* w_out = (const float*)d_in[2];
    const float* b_out = (const float*)d_in[3];
    float* out = (float*)d_out;

    float *qkv, *att;
    cudaGetSymbolAddress((void**)&qkv, g_qkv);
    cudaGetSymbolAddress((void**)&att, g_att);

    // 1) QKV projection (tf32 mma, round-2 kernel)
    {
        dim3 grid(QKV_N / BN, ROWS / BM);
        tf32_gemm_kernel<<<grid, 256>>>(x, w_qkv, nullptr, qkv, ROWS, QKV_N, DMODEL);
    }

    // 2) Flash attention v6 (fp16 single mma, zero-shuffle PV)
    {
        cudaFuncSetAttribute(flash_tc_kernel,
                             cudaFuncAttributeMaxDynamicSharedMemorySize, FLASH_SMEM);
        dim3 grid(SEQ / FBM, BATCH * NHEADS);
        flash_tc_kernel<<<grid, 256, FLASH_SMEM>>>(qkv, att);
    }

    // 3) Output projection + bias
    {
        dim3 grid(DMODEL / BN, ROWS / BM);
        tf32_gemm_kernel<<<grid, 256>>>(att, w_out, b_out, out, ROWS, DMODEL, DMODEL);
    }
}

// round 13
// speedup vs baseline: 1.5692x; 1.1560x over previous
#include <cuda_runtime.h>
#include <cuda_bf16.h>
#include <cuda_fp16.h>
#include <cstdint>

// Problem constants
#define BATCH 4
#define SEQ   2048
#define DMODEL 1024
#define NHEADS 16
#define HD    64
#define ROWS  (BATCH * SEQ)          // 8192
#define QKV_N (3 * DMODEL)           // 3072

// Scratch (allocation-free rule: __device__ globals)
__device__ float g_qkv[(size_t)ROWS * QKV_N];
__device__ float g_att[(size_t)ROWS * DMODEL];

// ---------------------------------------------------------------------------
// helpers
// ---------------------------------------------------------------------------
__device__ __forceinline__ void mma_f16(float& d0, float& d1, float& d2, float& d3,
                                        uint32_t a0, uint32_t a1, uint32_t a2, uint32_t a3,
                                        uint32_t b0, uint32_t b1)
{
    asm volatile(
        "mma.sync.aligned.m16n8k16.row.col.f32.f16.f16.f32 "
        "{%0,%1,%2,%3}, {%4,%5,%6,%7}, {%8,%9}, {%0,%1,%2,%3};"
        : "+f"(d0), "+f"(d1), "+f"(d2), "+f"(d3)
        : "r"(a0), "r"(a1), "r"(a2), "r"(a3), "r"(b0), "r"(b1));
}

// pack two floats -> f16x2 (lo = a, hi = b)
__device__ __forceinline__ uint32_t h2pack(float a, float b) {
    __half2 h = __floats2half2_rn(a, b);
    return *reinterpret_cast<uint32_t*>(&h);
}

// ---------------------------------------------------------------------------
// FP16 GEMM: C[M,N] = A[M,K] @ B[K,N] (+bias), fp32 accumulate.
// Structure = proven round-2 kernel (128x128 tile, BK=16, register prefetch,
// cvt at STS time), but f16x2-packed operands + mma.m16n8k16 -> HALF the mma
// instructions of the tf32 version at identical mantissa width.
// A packed [128 rows][8 k2] stride 12 (banks 12r+c distinct per phase);
// B packed [8 k2][128 n] stride 136 (banks 8c+n distinct).
// ---------------------------------------------------------------------------
#define BM 128
#define BN 128
#define APST 12
#define BPST 136

__global__ void __launch_bounds__(256, 2) f16_gemm_kernel(
    const float* __restrict__ A, const float* __restrict__ B,
    const float* __restrict__ bias, float* __restrict__ C,
    int M, int N, int K)
{
    __shared__ uint32_t Ap[BM * APST];   // [row][k2 0..7], f16x2 along K
    __shared__ uint32_t Bp[8 * BPST];    // [k2][n], pairs across adjacent k rows

    const int tid  = threadIdx.x;
    const int lane = tid & 31;
    const int warp = tid >> 5;
    const int brow = blockIdx.y;
    const int bcol = blockIdx.x;

    // A loader: 2 threads/row, each 8 consecutive floats (2 float4 -> 4 u32)
    const int am0 = tid >> 1;
    const int af0 = (tid & 1) * 8;       // float offset
    const int au0 = (tid & 1) * 4;       // u32 offset
    // B loader: thread handles k-pair k2=tid>>5, cols (tid&31)*4 .. +3
    const int bk2 = tid >> 5;
    const int bn0 = (tid & 31) * 4;

    const int wrow = warp >> 2;
    const int wcol = warp & 3;
    const int mbase = wrow * 64;
    const int nbase = wcol * 32;
    const int r = lane >> 2;
    const int c = lane & 3;

    const float* Ab = A + (size_t)(brow * BM + am0) * K + af0;
    const float* Bb = B + (size_t)(2 * bk2) * N + bcol * BN + bn0;

    float acc[4][4][4];
    #pragma unroll
    for (int i = 0; i < 4; i++)
        #pragma unroll
        for (int j = 0; j < 4; j++)
            #pragma unroll
            for (int t = 0; t < 4; t++) acc[i][j][t] = 0.f;

    float4 pa0 = *(const float4*)(Ab);
    float4 pa1 = *(const float4*)(Ab + 4);
    float4 pb0 = *(const float4*)(Bb);
    float4 pb1 = *(const float4*)(Bb + N);

    for (int k0 = 0; k0 < K; k0 += 16) {
        // pack + store tiles
        Ap[am0 * APST + au0 + 0] = h2pack(pa0.x, pa0.y);
        Ap[am0 * APST + au0 + 1] = h2pack(pa0.z, pa0.w);
        Ap[am0 * APST + au0 + 2] = h2pack(pa1.x, pa1.y);
        Ap[am0 * APST + au0 + 3] = h2pack(pa1.z, pa1.w);
        Bp[bk2 * BPST + bn0 + 0] = h2pack(pb0.x, pb1.x);
        Bp[bk2 * BPST + bn0 + 1] = h2pack(pb0.y, pb1.y);
        Bp[bk2 * BPST + bn0 + 2] = h2pack(pb0.z, pb1.z);
        Bp[bk2 * BPST + bn0 + 3] = h2pack(pb0.w, pb1.w);
        __syncthreads();

        // prefetch next chunk (overlaps compute)
        if (k0 + 16 < K) {
            pa0 = *(const float4*)(Ab + k0 + 16);
            pa1 = *(const float4*)(Ab + k0 + 20);
            pb0 = *(const float4*)(Bb + (size_t)(k0 + 16) * N);
            pb1 = *(const float4*)(Bb + (size_t)(k0 + 17) * N);
        }

        // one k16 step: 16 mmas
        uint32_t af[4][4];
        #pragma unroll
        for (int mt = 0; mt < 4; mt++) {
            const int m = mbase + mt * 16;
            af[mt][0] = Ap[(m + r) * APST + c];
            af[mt][1] = Ap[(m + r + 8) * APST + c];
            af[mt][2] = Ap[(m + r) * APST + c + 4];
            af[mt][3] = Ap[(m + r + 8) * APST + c + 4];
        }
        uint32_t bf[4][2];
        #pragma unroll
        for (int nt = 0; nt < 4; nt++) {
            const int n = nbase + nt * 8 + r;
            bf[nt][0] = Bp[c * BPST + n];
            bf[nt][1] = Bp[(c + 4) * BPST + n];
        }
        #pragma unroll
        for (int mt = 0; mt < 4; mt++)
            #pragma unroll
            for (int nt = 0; nt < 4; nt++)
                mma_f16(acc[mt][nt][0], acc[mt][nt][1],
                        acc[mt][nt][2], acc[mt][nt][3],
                        af[mt][0], af[mt][1], af[mt][2], af[mt][3],
                        bf[nt][0], bf[nt][1]);
        __syncthreads();
    }

    #pragma unroll
    for (int mt = 0; mt < 4; mt++) {
        const int row0 = brow * BM + mbase + mt * 16 + r;
        #pragma unroll
        for (int nt = 0; nt < 4; nt++) {
            const int col = bcol * BN + nbase + nt * 8 + 2 * c;
            float2 v0 = make_float2(acc[mt][nt][0], acc[mt][nt][1]);
            float2 v1 = make_float2(acc[mt][nt][2], acc[mt][nt][3]);
            if (bias) {
                float2 bb = *(const float2*)(bias + col);
                v0.x += bb.x; v0.y += bb.y;
                v1.x += bb.x; v1.y += bb.y;
            }
            *(float2*)(C + (size_t)row0 * N + col)       = v0;
            *(float2*)(C + (size_t)(row0 + 8) * N + col) = v1;
        }
    }
}

// ---------------------------------------------------------------------------
// Flash attention v6 (round-12 winner, byte-identical): fp16 single mma,
// zero-shuffle PV, smem 36864 B -> 2 CTAs/SM.
// ---------------------------------------------------------------------------
#define FBM 128
#define FBN 64
#define QPST 36
#define KPST 36
#define VPST 72
#define FLASH_SMEM ((FBM*QPST + FBN*KPST + 32*VPST) * 4)   // 36864 B

__global__ void __launch_bounds__(256, 2) flash_tc_kernel(
    const float* __restrict__ qkv, float* __restrict__ out)
{
    extern __shared__ uint32_t smf[];
    uint32_t* Qp = smf;
    uint32_t* Kp = Qp + FBM * QPST;
    uint32_t* Vp = Kp + FBN * KPST;

    const int tid  = threadIdx.x;
    const int lane = tid & 31;
    const int warp = tid >> 5;
    const int qt = (int)gridDim.x - 1 - (int)blockIdx.x;
    const int bh = blockIdx.y;
    const int b  = bh >> 4;
    const int h  = bh & 15;

    const size_t rs = (size_t)QKV_N;
    const float* qb = qkv + (size_t)b * SEQ * rs + h * HD;
    const float* kb = qb + DMODEL;
    const float* vb = qb + 2 * DMODEL;
    const int q0 = qt * FBM;

    for (int idx = tid; idx < FBM * 32; idx += 256) {
        const int row = idx >> 5, j = idx & 31;
        float2 q = *(const float2*)(qb + (size_t)(q0 + row) * rs + 2 * j);
        Qp[row * QPST + j] = h2pack(q.x, q.y);
    }

    const int r = lane >> 2;
    const int c = lane & 3;
    const int m0 = warp * 16;

    float o[8][4];
    #pragma unroll
    for (int nt = 0; nt < 8; nt++)
        #pragma unroll
        for (int t = 0; t < 4; t++) o[nt][t] = 0.f;
    float mx0 = -1e30f, mx1 = -1e30f, l0 = 0.f, l1 = 0.f;
    const float sl2e = 0.125f * 1.4426950408889634f;

    const int nkt = 2 * qt + 2;
    for (int kt = 0; kt < nkt; kt++) {
        __syncthreads();

        for (int idx = tid; idx < FBN * 32; idx += 256) {
            const int row = idx >> 5, j = idx & 31;
            float2 kv = *(const float2*)(kb + (size_t)(kt * FBN + row) * rs + 2 * j);
            Kp[row * KPST + j] = h2pack(kv.x, kv.y);
        }
        for (int idx = tid; idx < 32 * 16; idx += 256) {
            const int k2 = idx >> 4, j4 = (idx & 15) * 4;
            const float* v0p = vb + (size_t)(kt * FBN + 2 * k2) * rs + j4;
            float4 a = *(const float4*)v0p;
            float4 d = *(const float4*)(v0p + rs);
            Vp[k2 * VPST + j4 + 0] = h2pack(a.x, d.x);
            Vp[k2 * VPST + j4 + 1] = h2pack(a.y, d.y);
            Vp[k2 * VPST + j4 + 2] = h2pack(a.z, d.z);
            Vp[k2 * VPST + j4 + 3] = h2pack(a.w, d.w);
        }
        __syncthreads();

        float s[8][4];
        #pragma unroll
        for (int nt = 0; nt < 8; nt++)
            #pragma unroll
            for (int t = 0; t < 4; t++) s[nt][t] = 0.f;

        #pragma unroll
        for (int g = 0; g < 4; g++) {
            const int qo = 8 * g + c;
            uint32_t a0 = Qp[(m0 + r) * QPST + qo];
            uint32_t a1 = Qp[(m0 + r + 8) * QPST + qo];
            uint32_t a2 = Qp[(m0 + r) * QPST + qo + 4];
            uint32_t a3 = Qp[(m0 + r + 8) * QPST + qo + 4];
            #pragma unroll
            for (int nt = 0; nt < 8; nt++) {
                const int n = nt * 8 + r;
                uint32_t b0 = Kp[n * KPST + qo];
                uint32_t b1 = Kp[n * KPST + qo + 4];
                mma_f16(s[nt][0], s[nt][1], s[nt][2], s[nt][3], a0, a1, a2, a3, b0, b1);
            }
        }

        if (kt >= 2 * qt) {
            const int q0i = q0 + m0 + r;
            #pragma unroll
            for (int nt = 0; nt < 8; nt++) {
                int k0i = kt * FBN + nt * 8 + 2 * c;
                if (k0i     > q0i)     s[nt][0] = -1e30f;
                if (k0i + 1 > q0i)     s[nt][1] = -1e30f;
                if (k0i     > q0i + 8) s[nt][2] = -1e30f;
                if (k0i + 1 > q0i + 8) s[nt][3] = -1e30f;
            }
        }

        {
            float t = -1e30f;
            #pragma unroll
            for (int nt = 0; nt < 8; nt++) t = fmaxf(t, fmaxf(s[nt][0], s[nt][1]));
            t = fmaxf(t, __shfl_xor_sync(0xffffffffu, t, 1));
            t = fmaxf(t, __shfl_xor_sync(0xffffffffu, t, 2));
            t *= sl2e;
            float mn = fmaxf(mx0, t);
            float alpha = exp2f(mx0 - mn);
            float ps = 0.f;
            #pragma unroll
            for (int nt = 0; nt < 8; nt++) {
                float p0 = exp2f(s[nt][0] * sl2e - mn);
                float p1 = exp2f(s[nt][1] * sl2e - mn);
                s[nt][0] = p0; s[nt][1] = p1; ps += p0 + p1;
            }
            ps += __shfl_xor_sync(0xffffffffu, ps, 1);
            ps += __shfl_xor_sync(0xffffffffu, ps, 2);
            l0 = l0 * alpha + ps; mx0 = mn;
            #pragma unroll
            for (int nt = 0; nt < 8; nt++) { o[nt][0] *= alpha; o[nt][1] *= alpha; }
        }
        {
            float t = -1e30f;
            #pragma unroll
            for (int nt = 0; nt < 8; nt++) t = fmaxf(t, fmaxf(s[nt][2], s[nt][3]));
            t = fmaxf(t, __shfl_xor_sync(0xffffffffu, t, 1));
            t = fmaxf(t, __shfl_xor_sync(0xffffffffu, t, 2));
            t *= sl2e;
            float mn = fmaxf(mx1, t);
            float alpha = exp2f(mx1 - mn);
            float ps = 0.f;
            #pragma unroll
            for (int nt = 0; nt < 8; nt++) {
                float p0 = exp2f(s[nt][2] * sl2e - mn);
                float p1 = exp2f(s[nt][3] * sl2e - mn);
                s[nt][2] = p0; s[nt][3] = p1; ps += p0 + p1;
            }
            ps += __shfl_xor_sync(0xffffffffu, ps, 1);
            ps += __shfl_xor_sync(0xffffffffu, ps, 2);
            l1 = l1 * alpha + ps; mx1 = mn;
            #pragma unroll
            for (int nt = 0; nt < 8; nt++) { o[nt][2] *= alpha; o[nt][3] *= alpha; }
        }

        #pragma unroll
        for (int kk = 0; kk < 4; kk++) {
            uint32_t a0 = h2pack(s[2 * kk][0],     s[2 * kk][1]);
            uint32_t a1 = h2pack(s[2 * kk][2],     s[2 * kk][3]);
            uint32_t a2 = h2pack(s[2 * kk + 1][0], s[2 * kk + 1][1]);
            uint32_t a3 = h2pack(s[2 * kk + 1][2], s[2 * kk + 1][3]);
            #pragma unroll
            for (int nt = 0; nt < 8; nt++) {
                const int n = nt * 8 + r;
                uint32_t b0 = Vp[(8 * kk + c) * VPST + n];
                uint32_t b1 = Vp[(8 * kk + c + 4) * VPST + n];
                mma_f16(o[nt][0], o[nt][1], o[nt][2], o[nt][3], a0, a1, a2, a3, b0, b1);
            }
        }
    }

    const float inv0 = 1.f / l0;
    const float inv1 = 1.f / l1;
    const size_t row0 = (size_t)(b * SEQ + q0 + m0 + r) * DMODEL + h * HD;
    const size_t row1 = row0 + (size_t)8 * DMODEL;
    #pragma unroll
    for (int nt = 0; nt < 8; nt++) {
        const int col = nt * 8 + 2 * c;
        *(float2*)(out + row0 + col) = make_float2(o[nt][0] * inv0, o[nt][1] * inv0);
        *(float2*)(out + row1 + col) = make_float2(o[nt][2] * inv1, o[nt][3] * inv1);
    }
}

// ---------------------------------------------------------------------------
extern "C" void kernel_launch(void* const* d_in, const int* in_sizes, int n_in,
                              void* d_out, int out_size)
{
    const float* x     = (const float*)d_in[0];
    const float* w_qkv = (const float*)d_in[1];
    const float* w_out = (const float*)d_in[2];
    const float* b_out = (const float*)d_in[3];
    float* out = (float*)d_out;

    float *qkv, *att;
    cudaGetSymbolAddress((void**)&qkv, g_qkv);
    cudaGetSymbolAddress((void**)&att, g_att);

    // 1) QKV projection (fp16 mma.m16n8k16)
    {
        dim3 grid(QKV_N / BN, ROWS / BM);
        f16_gemm_kernel<<<grid, 256>>>(x, w_qkv, nullptr, qkv, ROWS, QKV_N, DMODEL);
    }

    // 2) Flash attention v6 (fp16 single mma, zero-shuffle PV)
    {
        cudaFuncSetAttribute(flash_tc_kernel,
                             cudaFuncAttributeMaxDynamicSharedMemorySize, FLASH_SMEM);
        dim3 grid(SEQ / FBM, BATCH * NHEADS);
        flash_tc_kernel<<<grid, 256, FLASH_SMEM>>>(qkv, att);
    }

    // 3) Output projection + bias (fp16)
    {
        dim3 grid(DMODEL / BN, ROWS / BM);
        f16_gemm_kernel<<<grid, 256>>>(att, w_out, b_out, out, ROWS, DMODEL, DMODEL);
    }
}

// round 14
// speedup vs baseline: 1.8553x; 1.1823x over previous
#include <cuda_runtime.h>
#include <cuda_bf16.h>
#include <cuda_fp16.h>
#include <cstdint>

// Problem constants
#define BATCH 4
#define SEQ   2048
#define DMODEL 1024
#define NHEADS 16
#define HD    64
#define ROWS  (BATCH * SEQ)          // 8192
#define QKV_N (3 * DMODEL)           // 3072

// Scratch (allocation-free rule: __device__ globals)
__device__ float  g_qkv[(size_t)ROWS * QKV_N];
__device__ __half g_xh[(size_t)ROWS * DMODEL];        // x as fp16 [M][K]
__device__ __half g_wqh[(size_t)QKV_N * DMODEL];      // w_qkv^T fp16 [N][K]
__device__ __half g_woh[(size_t)DMODEL * DMODEL];     // w_out^T fp16 [N][K]
__device__ __half g_ath[(size_t)ROWS * DMODEL];       // att as fp16 [M][K]

// ---------------------------------------------------------------------------
// helpers
// ---------------------------------------------------------------------------
__device__ __forceinline__ uint32_t s2u(const void* p) {
    uint32_t a;
    asm("{ .reg .u64 t; cvta.to.shared.u64 t, %1; cvt.u32.u64 %0, t; }"
        : "=r"(a) : "l"(p));
    return a;
}
__device__ __forceinline__ void mma_f16(float& d0, float& d1, float& d2, float& d3,
                                        uint32_t a0, uint32_t a1, uint32_t a2, uint32_t a3,
                                        uint32_t b0, uint32_t b1)
{
    asm volatile(
        "mma.sync.aligned.m16n8k16.row.col.f32.f16.f16.f32 "
        "{%0,%1,%2,%3}, {%4,%5,%6,%7}, {%8,%9}, {%0,%1,%2,%3};"
        : "+f"(d0), "+f"(d1), "+f"(d2), "+f"(d3)
        : "r"(a0), "r"(a1), "r"(a2), "r"(a3), "r"(b0), "r"(b1));
}
__device__ __forceinline__ void ldmx4(uint32_t* r, uint32_t addr) {
    asm volatile("ldmatrix.sync.aligned.m8n8.x4.shared.b16 {%0,%1,%2,%3}, [%4];"
                 : "=r"(r[0]), "=r"(r[1]), "=r"(r[2]), "=r"(r[3]) : "r"(addr));
}
__device__ __forceinline__ void cpasync16(uint32_t dst, const void* src) {
    asm volatile("cp.async.cg.shared.global [%0], [%1], 16;" :: "r"(dst), "l"(src));
}
#define CP_COMMIT() asm volatile("cp.async.commit_group;" ::: "memory")
#define CP_WAIT0()  asm volatile("cp.async.wait_group 0;" ::: "memory")
#define CP_WAIT1()  asm volatile("cp.async.wait_group 1;" ::: "memory")

__device__ __forceinline__ uint32_t h2pack(float a, float b) {
    __half2 h = __floats2half2_rn(a, b);
    return *reinterpret_cast<uint32_t*>(&h);
}

// ---------------------------------------------------------------------------
// prep kernels: fp32 -> fp16 (plain and transposed)
// ---------------------------------------------------------------------------
__global__ void cvt_f16_kernel(const float* __restrict__ in,
                               __half* __restrict__ out, int n4)
{
    int i = blockIdx.x * blockDim.x + threadIdx.x;
    if (i >= n4) return;
    float4 v = *(const float4*)(in + (size_t)i * 4);
    *(__half2*)(out + (size_t)i * 4)     = __floats2half2_rn(v.x, v.y);
    *(__half2*)(out + (size_t)i * 4 + 2) = __floats2half2_rn(v.z, v.w);
}

// in[K][N] fp32 -> out[N][K] fp16
__global__ void cvt_tr_f16_kernel(const float* __restrict__ in,
                                  __half* __restrict__ out, int K, int N)
{
    __shared__ float t[32][33];
    const int n0 = blockIdx.x * 32, k0 = blockIdx.y * 32;
    const int tx = threadIdx.x, ty = threadIdx.y;
    #pragma unroll
    for (int r = 0; r < 4; r++)
        t[ty + 8 * r][tx] = in[(size_t)(k0 + ty + 8 * r) * N + n0 + tx];
    __syncthreads();
    #pragma unroll
    for (int r = 0; r < 4; r++)
        out[(size_t)(n0 + ty + 8 * r) * K + k0 + tx] = __float2half_rn(t[tx][ty + 8 * r]);
}

// ---------------------------------------------------------------------------
// FP16 GEMM v2: C[M,N] = A[M,K] @ B[N,K]^T (+bias), fp32 accumulate.
// Round-7 pipeline (cp.async 2-stage + ldmatrix.x4, RST=40 conflict-free
// layout, proven 70K instr/us) with SINGLE fp16 mma per k16 (1/3 the instrs).
// 128x128 block tile, BK=32, 8 warps (2x4), warp tile 64x32.
// ---------------------------------------------------------------------------
#define RST   40                         // smem row stride in halves (80 B)
#define ARR_B (128 * RST * 2)            // 10240 B per array
#define STG_B (2 * ARR_B)                // 20480 B per stage (A|B)
#define GEMM_SMEM (2 * STG_B)            // 40960 B

__global__ void __launch_bounds__(256, 2) f16_gemm_kernel(
    const __half* __restrict__ A, const __half* __restrict__ Bt,
    const float* __restrict__ bias, float* __restrict__ C,
    int M, int N, int K)
{
    extern __shared__ char smem2[];
    const uint32_t sb = s2u(smem2);

    const int tid  = threadIdx.x;
    const int lane = tid & 31;
    const int warp = tid >> 5;
    const int m0 = blockIdx.y * 128;
    const int n0 = blockIdx.x * 128;

    const int wrow = warp >> 2;
    const int wcol = warp & 3;
    const int mbase = wrow * 64;
    const int nbase = wcol * 32;
    const int r = lane >> 2;
    const int c = lane & 3;
    const int lr = lane & 15;          // ldmatrix row select
    const int lc = lane >> 4;          // ldmatrix k-chunk select

    const __half* srcs[2] = { A + (size_t)m0 * K, Bt + (size_t)n0 * K };

    float acc[4][4][4];
    #pragma unroll
    for (int i = 0; i < 4; i++)
        #pragma unroll
        for (int j = 0; j < 4; j++)
            #pragma unroll
            for (int t = 0; t < 4; t++) acc[i][j][t] = 0.f;

    // one chunk = 32 k-cols of both arrays (8 KB fp16 data). 4 cp.async/thread.
    auto load_chunk = [&](int kc, int buf) {
        const uint32_t bb = sb + buf * STG_B;
        #pragma unroll
        for (int u = 0; u < 4; u++) {
            const int arr = u >> 1;
            const int w = (u & 1) * 256 + tid;      // 0..511
            const int row = w >> 2, j = w & 3;
            cpasync16(bb + arr * ARR_B + row * (RST * 2) + j * 16,
                      srcs[arr] + (size_t)row * K + kc * 32 + j * 8);
        }
        CP_COMMIT();
    };

    const int NCH = K / 32;
    load_chunk(0, 0);
    load_chunk(1, 1);

    for (int i = 0; i < NCH; i++) {
        const int buf = i & 1;
        if (i + 1 < NCH) { CP_WAIT1(); } else { CP_WAIT0(); }
        __syncthreads();

        const uint32_t baseA = sb + buf * STG_B;
        const uint32_t baseB = baseA + ARR_B;

        #pragma unroll
        for (int ks = 0; ks < 2; ks++) {
            const uint32_t ko = ks * 32;    // k16 chunk byte offset
            uint32_t ah[4][4], bh[2][4];
            #pragma unroll
            for (int mt = 0; mt < 4; mt++) {
                const uint32_t ro = (uint32_t)(mbase + mt * 16 + lr) * (RST * 2) + ko + lc * 16;
                ldmx4(ah[mt], baseA + ro);
            }
            #pragma unroll
            for (int p = 0; p < 2; p++) {
                const uint32_t ro = (uint32_t)(nbase + p * 16 + lr) * (RST * 2) + ko + lc * 16;
                ldmx4(bh[p], baseB + ro);
            }
            #pragma unroll
            for (int mt = 0; mt < 4; mt++)
                #pragma unroll
                for (int nt = 0; nt < 4; nt++) {
                    const int p = nt >> 1, q = nt & 1;
                    mma_f16(acc[mt][nt][0], acc[mt][nt][1], acc[mt][nt][2], acc[mt][nt][3],
                            ah[mt][0], ah[mt][1], ah[mt][2], ah[mt][3],
                            bh[p][q], bh[p][q + 2]);
                }
        }
        __syncthreads();
        if (i + 2 < NCH) load_chunk(i + 2, buf);
    }

    // epilogue (round-7 scheme, proven)
    #pragma unroll
    for (int mt = 0; mt < 4; mt++) {
        const int row0 = m0 + mbase + mt * 16 + r;
        #pragma unroll
        for (int nt = 0; nt < 4; nt++) {
            const int col = n0 + nbase + nt * 8 + 2 * c;
            float2 v0 = make_float2(acc[mt][nt][0], acc[mt][nt][1]);
            float2 v1 = make_float2(acc[mt][nt][2], acc[mt][nt][3]);
            if (bias) {
                float2 bb = *(const float2*)(bias + col);
                v0.x += bb.x; v0.y += bb.y;
                v1.x += bb.x; v1.y += bb.y;
            }
            *(float2*)(C + (size_t)row0 * N + col)       = v0;
            *(float2*)(C + (size_t)(row0 + 8) * N + col) = v1;
        }
    }
}

// ---------------------------------------------------------------------------
// Flash attention v6 (round-12 winner): fp16 single mma, zero-shuffle PV.
// Only change: epilogue writes fp16 att (operand for the fp16 out-proj).
// smem 36864 B -> 2 CTAs/SM.
// ---------------------------------------------------------------------------
#define FBM 128
#define FBN 64
#define QPST 36
#define KPST 36
#define VPST 72
#define FLASH_SMEM ((FBM*QPST + FBN*KPST + 32*VPST) * 4)   // 36864 B

__global__ void __launch_bounds__(256, 2) flash_tc_kernel(
    const float* __restrict__ qkv, __half* __restrict__ out)
{
    extern __shared__ uint32_t smf[];
    uint32_t* Qp = smf;
    uint32_t* Kp = Qp + FBM * QPST;
    uint32_t* Vp = Kp + FBN * KPST;

    const int tid  = threadIdx.x;
    const int lane = tid & 31;
    const int warp = tid >> 5;
    const int qt = (int)gridDim.x - 1 - (int)blockIdx.x;
    const int bh = blockIdx.y;
    const int b  = bh >> 4;
    const int h  = bh & 15;

    const size_t rs = (size_t)QKV_N;
    const float* qb = qkv + (size_t)b * SEQ * rs + h * HD;
    const float* kb = qb + DMODEL;
    const float* vb = qb + 2 * DMODEL;
    const int q0 = qt * FBM;

    for (int idx = tid; idx < FBM * 32; idx += 256) {
        const int row = idx >> 5, j = idx & 31;
        float2 q = *(const float2*)(qb + (size_t)(q0 + row) * rs + 2 * j);
        Qp[row * QPST + j] = h2pack(q.x, q.y);
    }

    const int r = lane >> 2;
    const int c = lane & 3;
    const int m0 = warp * 16;

    float o[8][4];
    #pragma unroll
    for (int nt = 0; nt < 8; nt++)
        #pragma unroll
        for (int t = 0; t < 4; t++) o[nt][t] = 0.f;
    float mx0 = -1e30f, mx1 = -1e30f, l0 = 0.f, l1 = 0.f;
    const float sl2e = 0.125f * 1.4426950408889634f;

    const int nkt = 2 * qt + 2;
    for (int kt = 0; kt < nkt; kt++) {
        __syncthreads();

        for (int idx = tid; idx < FBN * 32; idx += 256) {
            const int row = idx >> 5, j = idx & 31;
            float2 kv = *(const float2*)(kb + (size_t)(kt * FBN + row) * rs + 2 * j);
            Kp[row * KPST + j] = h2pack(kv.x, kv.y);
        }
        for (int idx = tid; idx < 32 * 16; idx += 256) {
            const int k2 = idx >> 4, j4 = (idx & 15) * 4;
            const float* v0p = vb + (size_t)(kt * FBN + 2 * k2) * rs + j4;
            float4 a = *(const float4*)v0p;
            float4 d = *(const float4*)(v0p + rs);
            Vp[k2 * VPST + j4 + 0] = h2pack(a.x, d.x);
            Vp[k2 * VPST + j4 + 1] = h2pack(a.y, d.y);
            Vp[k2 * VPST + j4 + 2] = h2pack(a.z, d.z);
            Vp[k2 * VPST + j4 + 3] = h2pack(a.w, d.w);
        }
        __syncthreads();

        float s[8][4];
        #pragma unroll
        for (int nt = 0; nt < 8; nt++)
            #pragma unroll
            for (int t = 0; t < 4; t++) s[nt][t] = 0.f;

        #pragma unroll
        for (int g = 0; g < 4; g++) {
            const int qo = 8 * g + c;
            uint32_t a0 = Qp[(m0 + r) * QPST + qo];
            uint32_t a1 = Qp[(m0 + r + 8) * QPST + qo];
            uint32_t a2 = Qp[(m0 + r) * QPST + qo + 4];
            uint32_t a3 = Qp[(m0 + r + 8) * QPST + qo + 4];
            #pragma unroll
            for (int nt = 0; nt < 8; nt++) {
                const int n = nt * 8 + r;
                uint32_t b0 = Kp[n * KPST + qo];
                uint32_t b1 = Kp[n * KPST + qo + 4];
                mma_f16(s[nt][0], s[nt][1], s[nt][2], s[nt][3], a0, a1, a2, a3, b0, b1);
            }
        }

        if (kt >= 2 * qt) {
            const int q0i = q0 + m0 + r;
            #pragma unroll
            for (int nt = 0; nt < 8; nt++) {
                int k0i = kt * FBN + nt * 8 + 2 * c;
                if (k0i     > q0i)     s[nt][0] = -1e30f;
                if (k0i + 1 > q0i)     s[nt][1] = -1e30f;
                if (k0i     > q0i + 8) s[nt][2] = -1e30f;
                if (k0i + 1 > q0i + 8) s[nt][3] = -1e30f;
            }
        }

        {
            float t = -1e30f;
            #pragma unroll
            for (int nt = 0; nt < 8; nt++) t = fmaxf(t, fmaxf(s[nt][0], s[nt][1]));
            t = fmaxf(t, __shfl_xor_sync(0xffffffffu, t, 1));
            t = fmaxf(t, __shfl_xor_sync(0xffffffffu, t, 2));
            t *= sl2e;
            float mn = fmaxf(mx0, t);
            float alpha = exp2f(mx0 - mn);
            float ps = 0.f;
            #pragma unroll
            for (int nt = 0; nt < 8; nt++) {
                float p0 = exp2f(s[nt][0] * sl2e - mn);
                float p1 = exp2f(s[nt][1] * sl2e - mn);
                s[nt][0] = p0; s[nt][1] = p1; ps += p0 + p1;
            }
            ps += __shfl_xor_sync(0xffffffffu, ps, 1);
            ps += __shfl_xor_sync(0xffffffffu, ps, 2);
            l0 = l0 * alpha + ps; mx0 = mn;
            #pragma unroll
            for (int nt = 0; nt < 8; nt++) { o[nt][0] *= alpha; o[nt][1] *= alpha; }
        }
        {
            float t = -1e30f;
            #pragma unroll
            for (int nt = 0; nt < 8; nt++) t = fmaxf(t, fmaxf(s[nt][2], s[nt][3]));
            t = fmaxf(t, __shfl_xor_sync(0xffffffffu, t, 1));
            t = fmaxf(t, __shfl_xor_sync(0xffffffffu, t, 2));
            t *= sl2e;
            float mn = fmaxf(mx1, t);
            float alpha = exp2f(mx1 - mn);
            float ps = 0.f;
            #pragma unroll
            for (int nt = 0; nt < 8; nt++) {
                float p0 = exp2f(s[nt][2] * sl2e - mn);
                float p1 = exp2f(s[nt][3] * sl2e - mn);
                s[nt][2] = p0; s[nt][3] = p1; ps += p0 + p1;
            }
            ps += __shfl_xor_sync(0xffffffffu, ps, 1);
            ps += __shfl_xor_sync(0xffffffffu, ps, 2);
            l1 = l1 * alpha + ps; mx1 = mn;
            #pragma unroll
            for (int nt = 0; nt < 8; nt++) { o[nt][2] *= alpha; o[nt][3] *= alpha; }
        }

        #pragma unroll
        for (int kk = 0; kk < 4; kk++) {
            uint32_t a0 = h2pack(s[2 * kk][0],     s[2 * kk][1]);
            uint32_t a1 = h2pack(s[2 * kk][2],     s[2 * kk][3]);
            uint32_t a2 = h2pack(s[2 * kk + 1][0], s[2 * kk + 1][1]);
            uint32_t a3 = h2pack(s[2 * kk + 1][2], s[2 * kk + 1][3]);
            #pragma unroll
            for (int nt = 0; nt < 8; nt++) {
                const int n = nt * 8 + r;
                uint32_t b0 = Vp[(8 * kk + c) * VPST + n];
                uint32_t b1 = Vp[(8 * kk + c + 4) * VPST + n];
                mma_f16(o[nt][0], o[nt][1], o[nt][2], o[nt][3], a0, a1, a2, a3, b0, b1);
            }
        }
    }

    // epilogue: normalize and write fp16 att
    const float inv0 = 1.f / l0;
    const float inv1 = 1.f / l1;
    const size_t row0 = (size_t)(b * SEQ + q0 + m0 + r) * DMODEL + h * HD;
    const size_t row1 = row0 + (size_t)8 * DMODEL;
    #pragma unroll
    for (int nt = 0; nt < 8; nt++) {
        const int col = nt * 8 + 2 * c;
        *(__half2*)(out + row0 + col) = __floats2half2_rn(o[nt][0] * inv0, o[nt][1] * inv0);
        *(__half2*)(out + row1 + col) = __floats2half2_rn(o[nt][2] * inv1, o[nt][3] * inv1);
    }
}

// ---------------------------------------------------------------------------
extern "C" void kernel_launch(void* const* d_in, const int* in_sizes, int n_in,
                              void* d_out, int out_size)
{
    const float* x     = (const float*)d_in[0];
    const float* w_qkv = (const float*)d_in[1];
    const float* w_out = (const float*)d_in[2];
    const float* b_out = (const float*)d_in[3];
    float* out = (float*)d_out;

    float* qkv;
    __half *xh, *wqh, *woh, *ath;
    cudaGetSymbolAddress((void**)&qkv, g_qkv);
    cudaGetSymbolAddress((void**)&xh,  g_xh);
    cudaGetSymbolAddress((void**)&wqh, g_wqh);
    cudaGetSymbolAddress((void**)&woh, g_woh);
    cudaGetSymbolAddress((void**)&ath, g_ath);

    // 0) prep: x -> fp16; weights -> transposed fp16 [N][K]
    {
        int n4 = ROWS * DMODEL / 4;
        cvt_f16_kernel<<<(n4 + 255) / 256, 256>>>(x, xh, n4);
        cvt_tr_f16_kernel<<<dim3(QKV_N / 32, DMODEL / 32), dim3(32, 8)>>>(w_qkv, wqh, DMODEL, QKV_N);
        cvt_tr_f16_kernel<<<dim3(DMODEL / 32, DMODEL / 32), dim3(32, 8)>>>(w_out, woh, DMODEL, DMODEL);
    }

    cudaFuncSetAttribute(f16_gemm_kernel,
                         cudaFuncAttributeMaxDynamicSharedMemorySize, GEMM_SMEM);

    // 1) QKV projection (fp16 mma + ldmatrix + cp.async)
    {
        dim3 grid(QKV_N / 128, ROWS / 128);
        f16_gemm_kernel<<<grid, 256, GEMM_SMEM>>>(xh, wqh, nullptr, qkv,
                                                  ROWS, QKV_N, DMODEL);
    }

    // 2) Flash attention v6 (fp16 single mma)
    {
        cudaFuncSetAttribute(flash_tc_kernel,
                             cudaFuncAttributeMaxDynamicSharedMemorySize, FLASH_SMEM);
        dim3 grid(SEQ / FBM, BATCH * NHEADS);
        flash_tc_kernel<<<grid, 256, FLASH_SMEM>>>(qkv, ath);
    }

    // 3) Output projection + bias (fp16)
    {
        dim3 grid(DMODEL / 128, ROWS / 128);
        f16_gemm_kernel<<<grid, 256, GEMM_SMEM>>>(ath, woh, b_out, out,
                                                  ROWS, DMODEL, DMODEL);
    }
}

// round 15
// speedup vs baseline: 2.2208x; 1.1971x over previous
#include <cuda_runtime.h>
#include <cuda_bf16.h>
#include <cuda_fp16.h>
#include <cstdint>

// Problem constants
#define BATCH 4
#define SEQ   2048
#define DMODEL 1024
#define NHEADS 16
#define HD    64
#define ROWS  (BATCH * SEQ)          // 8192
#define QKV_N (3 * DMODEL)           // 3072

// Scratch (allocation-free rule: __device__ globals)
__device__ __half g_qkvh[(size_t)ROWS * QKV_N];       // qkv as fp16
__device__ __half g_xh[(size_t)ROWS * DMODEL];        // x as fp16 [M][K]
__device__ __half g_wqh[(size_t)QKV_N * DMODEL];      // w_qkv^T fp16 [N][K]
__device__ __half g_woh[(size_t)DMODEL * DMODEL];     // w_out^T fp16 [N][K]
__device__ __half g_ath[(size_t)ROWS * DMODEL];       // att as fp16 [M][K]

// ---------------------------------------------------------------------------
// helpers
// ---------------------------------------------------------------------------
__device__ __forceinline__ uint32_t s2u(const void* p) {
    uint32_t a;
    asm("{ .reg .u64 t; cvta.to.shared.u64 t, %1; cvt.u32.u64 %0, t; }"
        : "=r"(a) : "l"(p));
    return a;
}
__device__ __forceinline__ void mma_f16(float& d0, float& d1, float& d2, float& d3,
                                        uint32_t a0, uint32_t a1, uint32_t a2, uint32_t a3,
                                        uint32_t b0, uint32_t b1)
{
    asm volatile(
        "mma.sync.aligned.m16n8k16.row.col.f32.f16.f16.f32 "
        "{%0,%1,%2,%3}, {%4,%5,%6,%7}, {%8,%9}, {%0,%1,%2,%3};"
        : "+f"(d0), "+f"(d1), "+f"(d2), "+f"(d3)
        : "r"(a0), "r"(a1), "r"(a2), "r"(a3), "r"(b0), "r"(b1));
}
__device__ __forceinline__ void ldmx4(uint32_t* r, uint32_t addr) {
    asm volatile("ldmatrix.sync.aligned.m8n8.x4.shared.b16 {%0,%1,%2,%3}, [%4];"
                 : "=r"(r[0]), "=r"(r[1]), "=r"(r[2]), "=r"(r[3]) : "r"(addr));
}
__device__ __forceinline__ void cpasync16(uint32_t dst, const void* src) {
    asm volatile("cp.async.cg.shared.global [%0], [%1], 16;" :: "r"(dst), "l"(src));
}
#define CP_COMMIT() asm volatile("cp.async.commit_group;" ::: "memory")
#define CP_WAIT0()  asm volatile("cp.async.wait_group 0;" ::: "memory")
#define CP_WAIT1()  asm volatile("cp.async.wait_group 1;" ::: "memory")

__device__ __forceinline__ uint32_t h2pack(float a, float b) {
    __half2 h = __floats2half2_rn(a, b);
    return *reinterpret_cast<uint32_t*>(&h);
}
// byte-mix two f16x2: (a.lo, b.lo) and (a.hi, b.hi)
__device__ __forceinline__ uint32_t prmt_lo(uint32_t a, uint32_t b) {
    uint32_t d; asm("prmt.b32 %0, %1, %2, 0x5410;" : "=r"(d) : "r"(a), "r"(b)); return d;
}
__device__ __forceinline__ uint32_t prmt_hi(uint32_t a, uint32_t b) {
    uint32_t d; asm("prmt.b32 %0, %1, %2, 0x7632;" : "=r"(d) : "r"(a), "r"(b)); return d;
}

// ---------------------------------------------------------------------------
// prep kernels: fp32 -> fp16 (plain and transposed)
// ---------------------------------------------------------------------------
__global__ void cvt_f16_kernel(const float* __restrict__ in,
                               __half* __restrict__ out, int n4)
{
    int i = blockIdx.x * blockDim.x + threadIdx.x;
    if (i >= n4) return;
    float4 v = *(const float4*)(in + (size_t)i * 4);
    *(__half2*)(out + (size_t)i * 4)     = __floats2half2_rn(v.x, v.y);
    *(__half2*)(out + (size_t)i * 4 + 2) = __floats2half2_rn(v.z, v.w);
}

// in[K][N] fp32 -> out[N][K] fp16
__global__ void cvt_tr_f16_kernel(const float* __restrict__ in,
                                  __half* __restrict__ out, int K, int N)
{
    __shared__ float t[32][33];
    const int n0 = blockIdx.x * 32, k0 = blockIdx.y * 32;
    const int tx = threadIdx.x, ty = threadIdx.y;
    #pragma unroll
    for (int r = 0; r < 4; r++)
        t[ty + 8 * r][tx] = in[(size_t)(k0 + ty + 8 * r) * N + n0 + tx];
    __syncthreads();
    #pragma unroll
    for (int r = 0; r < 4; r++)
        out[(size_t)(n0 + ty + 8 * r) * K + k0 + tx] = __float2half_rn(t[tx][ty + 8 * r]);
}

// ---------------------------------------------------------------------------
// FP16 GEMM (round-14 winner): cp.async 2-stage + ldmatrix.x4 + single fp16
// mma. Epilogue writes fp32 (Cf) or fp16 (Ch) — exactly one is non-null.
// ---------------------------------------------------------------------------
#define RST   40
#define ARR_B (128 * RST * 2)
#define STG_B (2 * ARR_B)
#define GEMM_SMEM (2 * STG_B)            // 40960 B

__global__ void __launch_bounds__(256, 2) f16_gemm_kernel(
    const __half* __restrict__ A, const __half* __restrict__ Bt,
    const float* __restrict__ bias,
    float* __restrict__ Cf, __half* __restrict__ Ch,
    int M, int N, int K)
{
    extern __shared__ char smem2[];
    const uint32_t sb = s2u(smem2);

    const int tid  = threadIdx.x;
    const int lane = tid & 31;
    const int warp = tid >> 5;
    const int m0 = blockIdx.y * 128;
    const int n0 = blockIdx.x * 128;

    const int wrow = warp >> 2;
    const int wcol = warp & 3;
    const int mbase = wrow * 64;
    const int nbase = wcol * 32;
    const int r = lane >> 2;
    const int c = lane & 3;
    const int lr = lane & 15;
    const int lc = lane >> 4;

    const __half* srcs[2] = { A + (size_t)m0 * K, Bt + (size_t)n0 * K };

    float acc[4][4][4];
    #pragma unroll
    for (int i = 0; i < 4; i++)
        #pragma unroll
        for (int j = 0; j < 4; j++)
            #pragma unroll
            for (int t = 0; t < 4; t++) acc[i][j][t] = 0.f;

    auto load_chunk = [&](int kc, int buf) {
        const uint32_t bb = sb + buf * STG_B;
        #pragma unroll
        for (int u = 0; u < 4; u++) {
            const int arr = u >> 1;
            const int w = (u & 1) * 256 + tid;
            const int row = w >> 2, j = w & 3;
            cpasync16(bb + arr * ARR_B + row * (RST * 2) + j * 16,
                      srcs[arr] + (size_t)row * K + kc * 32 + j * 8);
        }
        CP_COMMIT();
    };

    const int NCH = K / 32;
    load_chunk(0, 0);
    load_chunk(1, 1);

    for (int i = 0; i < NCH; i++) {
        const int buf = i & 1;
        if (i + 1 < NCH) { CP_WAIT1(); } else { CP_WAIT0(); }
        __syncthreads();

        const uint32_t baseA = sb + buf * STG_B;
        const uint32_t baseB = baseA + ARR_B;

        #pragma unroll
        for (int ks = 0; ks < 2; ks++) {
            const uint32_t ko = ks * 32;
            uint32_t ah[4][4], bh[2][4];
            #pragma unroll
            for (int mt = 0; mt < 4; mt++) {
                const uint32_t ro = (uint32_t)(mbase + mt * 16 + lr) * (RST * 2) + ko + lc * 16;
                ldmx4(ah[mt], baseA + ro);
            }
            #pragma unroll
            for (int p = 0; p < 2; p++) {
                const uint32_t ro = (uint32_t)(nbase + p * 16 + lr) * (RST * 2) + ko + lc * 16;
                ldmx4(bh[p], baseB + ro);
            }
            #pragma unroll
            for (int mt = 0; mt < 4; mt++)
                #pragma unroll
                for (int nt = 0; nt < 4; nt++) {
                    const int p = nt >> 1, q = nt & 1;
                    mma_f16(acc[mt][nt][0], acc[mt][nt][1], acc[mt][nt][2], acc[mt][nt][3],
                            ah[mt][0], ah[mt][1], ah[mt][2], ah[mt][3],
                            bh[p][q], bh[p][q + 2]);
                }
        }
        __syncthreads();
        if (i + 2 < NCH) load_chunk(i + 2, buf);
    }

    #pragma unroll
    for (int mt = 0; mt < 4; mt++) {
        const int row0 = m0 + mbase + mt * 16 + r;
        #pragma unroll
        for (int nt = 0; nt < 4; nt++) {
            const int col = n0 + nbase + nt * 8 + 2 * c;
            float2 v0 = make_float2(acc[mt][nt][0], acc[mt][nt][1]);
            float2 v1 = make_float2(acc[mt][nt][2], acc[mt][nt][3]);
            if (bias) {
                float2 bb = *(const float2*)(bias + col);
                v0.x += bb.x; v0.y += bb.y;
                v1.x += bb.x; v1.y += bb.y;
            }
            if (Ch) {
                *(__half2*)(Ch + (size_t)row0 * N + col)       = __floats2half2_rn(v0.x, v0.y);
                *(__half2*)(Ch + (size_t)(row0 + 8) * N + col) = __floats2half2_rn(v1.x, v1.y);
            } else {
                *(float2*)(Cf + (size_t)row0 * N + col)       = v0;
                *(float2*)(Cf + (size_t)(row0 + 8) * N + col) = v1;
            }
        }
    }
}

// ---------------------------------------------------------------------------
// Flash attention v7: compute path identical to v6 (fp16 single mma,
// zero-shuffle PV). Loader consumes fp16 qkv: Q/K pure cp.async (global
// layout == smem pair format), V via 2xPRMT interleave. smem 36864 B.
// ---------------------------------------------------------------------------
#define FBM 128
#define FBN 64
#define QPST 36
#define KPST 36
#define VPST 72
#define FLASH_SMEM ((FBM*QPST + FBN*KPST + 32*VPST) * 4)   // 36864 B

__global__ void __launch_bounds__(256, 2) flash_tc_kernel(
    const __half* __restrict__ qkvh, __half* __restrict__ out)
{
    extern __shared__ uint32_t smf[];
    uint32_t* Qp = smf;
    uint32_t* Kp = Qp + FBM * QPST;
    uint32_t* Vp = Kp + FBN * KPST;

    const int tid  = threadIdx.x;
    const int lane = tid & 31;
    const int warp = tid >> 5;
    const int qt = (int)gridDim.x - 1 - (int)blockIdx.x;
    const int bh = blockIdx.y;
    const int b  = bh >> 4;
    const int h  = bh & 15;

    const size_t rs = (size_t)QKV_N;
    const __half* qb = qkvh + (size_t)b * SEQ * rs + h * HD;
    const __half* kb = qb + DMODEL;
    const __half* vb = qb + 2 * DMODEL;
    const int q0 = qt * FBM;

    // ---- Q prologue: pure cp.async (fp16 pairs are already Qp format) ----
    for (int idx = tid; idx < FBM * 8; idx += 256) {
        const int row = idx >> 3, j4 = (idx & 7) * 4;   // 4 u32 = 8 halves
        cpasync16(s2u(&Qp[row * QPST + j4]),
                  qb + (size_t)(q0 + row) * rs + 8 * (idx & 7));
    }
    CP_COMMIT();

    const int r = lane >> 2;
    const int c = lane & 3;
    const int m0 = warp * 16;

    float o[8][4];
    #pragma unroll
    for (int nt = 0; nt < 8; nt++)
        #pragma unroll
        for (int t = 0; t < 4; t++) o[nt][t] = 0.f;
    float mx0 = -1e30f, mx1 = -1e30f, l0 = 0.f, l1 = 0.f;
    const float sl2e = 0.125f * 1.4426950408889634f;

    const int nkt = 2 * qt + 2;
    for (int kt = 0; kt < nkt; kt++) {
        __syncthreads();   // previous iter's readers done

        // K tile: pure cp.async
        for (int idx = tid; idx < FBN * 8; idx += 256) {
            const int row = idx >> 3, j4 = (idx & 7) * 4;
            cpasync16(s2u(&Kp[row * KPST + j4]),
                      kb + (size_t)(kt * FBN + row) * rs + 8 * (idx & 7));
        }
        CP_COMMIT();

        // V tile: fp16 loads + PRMT pair-interleave (2 PRMT per u32 out)
        for (int idx = tid; idx < 32 * 16; idx += 256) {
            const int k2 = idx >> 4, q4 = (idx & 15) * 4;   // output u32 cols q4..q4+3
            const uint32_t* rowA = (const uint32_t*)(vb + (size_t)(kt * FBN + 2 * k2) * rs) + (q4 >> 1);
            const uint32_t* rowD = (const uint32_t*)((const __half*)rowA + rs);
            uint2 A = *(const uint2*)rowA;
            uint2 D = *(const uint2*)rowD;
            Vp[k2 * VPST + q4 + 0] = prmt_lo(A.x, D.x);
            Vp[k2 * VPST + q4 + 1] = prmt_hi(A.x, D.x);
            Vp[k2 * VPST + q4 + 2] = prmt_lo(A.y, D.y);
            Vp[k2 * VPST + q4 + 3] = prmt_hi(A.y, D.y);
        }
        CP_WAIT0();   // K (and Q on iter 0) landed
        __syncthreads();

        // ---- S = Q @ K^T : fp16 single ----
        float s[8][4];
        #pragma unroll
        for (int nt = 0; nt < 8; nt++)
            #pragma unroll
            for (int t = 0; t < 4; t++) s[nt][t] = 0.f;

        #pragma unroll
        for (int g = 0; g < 4; g++) {
            const int qo = 8 * g + c;
            uint32_t a0 = Qp[(m0 + r) * QPST + qo];
            uint32_t a1 = Qp[(m0 + r + 8) * QPST + qo];
            uint32_t a2 = Qp[(m0 + r) * QPST + qo + 4];
            uint32_t a3 = Qp[(m0 + r + 8) * QPST + qo + 4];
            #pragma unroll
            for (int nt = 0; nt < 8; nt++) {
                const int n = nt * 8 + r;
                uint32_t b0 = Kp[n * KPST + qo];
                uint32_t b1 = Kp[n * KPST + qo + 4];
                mma_f16(s[nt][0], s[nt][1], s[nt][2], s[nt][3], a0, a1, a2, a3, b0, b1);
            }
        }

        // ---- causal mask ----
        if (kt >= 2 * qt) {
            const int q0i = q0 + m0 + r;
            #pragma unroll
            for (int nt = 0; nt < 8; nt++) {
                int k0i = kt * FBN + nt * 8 + 2 * c;
                if (k0i     > q0i)     s[nt][0] = -1e30f;
                if (k0i + 1 > q0i)     s[nt][1] = -1e30f;
                if (k0i     > q0i + 8) s[nt][2] = -1e30f;
                if (k0i + 1 > q0i + 8) s[nt][3] = -1e30f;
            }
        }

        // ---- online softmax: row r ----
        {
            float t = -1e30f;
            #pragma unroll
            for (int nt = 0; nt < 8; nt++) t = fmaxf(t, fmaxf(s[nt][0], s[nt][1]));
            t = fmaxf(t, __shfl_xor_sync(0xffffffffu, t, 1));
            t = fmaxf(t, __shfl_xor_sync(0xffffffffu, t, 2));
            t *= sl2e;
            float mn = fmaxf(mx0, t);
            float alpha = exp2f(mx0 - mn);
            float ps = 0.f;
            #pragma unroll
            for (int nt = 0; nt < 8; nt++) {
                float p0 = exp2f(s[nt][0] * sl2e - mn);
                float p1 = exp2f(s[nt][1] * sl2e - mn);
                s[nt][0] = p0; s[nt][1] = p1; ps += p0 + p1;
            }
            ps += __shfl_xor_sync(0xffffffffu, ps, 1);
            ps += __shfl_xor_sync(0xffffffffu, ps, 2);
            l0 = l0 * alpha + ps; mx0 = mn;
            #pragma unroll
            for (int nt = 0; nt < 8; nt++) { o[nt][0] *= alpha; o[nt][1] *= alpha; }
        }
        // ---- row r+8 ----
        {
            float t = -1e30f;
            #pragma unroll
            for (int nt = 0; nt < 8; nt++) t = fmaxf(t, fmaxf(s[nt][2], s[nt][3]));
            t = fmaxf(t, __shfl_xor_sync(0xffffffffu, t, 1));
            t = fmaxf(t, __shfl_xor_sync(0xffffffffu, t, 2));
            t *= sl2e;
            float mn = fmaxf(mx1, t);
            float alpha = exp2f(mx1 - mn);
            float ps = 0.f;
            #pragma unroll
            for (int nt = 0; nt < 8; nt++) {
                float p0 = exp2f(s[nt][2] * sl2e - mn);
                float p1 = exp2f(s[nt][3] * sl2e - mn);
                s[nt][2] = p0; s[nt][3] = p1; ps += p0 + p1;
            }
            ps += __shfl_xor_sync(0xffffffffu, ps, 1);
            ps += __shfl_xor_sync(0xffffffffu, ps, 2);
            l1 = l1 * alpha + ps; mx1 = mn;
            #pragma unroll
            for (int nt = 0; nt < 8; nt++) { o[nt][2] *= alpha; o[nt][3] *= alpha; }
        }

        // ---- O += P @ V : fp16, C-frag -> A-frag in-lane ----
        #pragma unroll
        for (int kk = 0; kk < 4; kk++) {
            uint32_t a0 = h2pack(s[2 * kk][0],     s[2 * kk][1]);
            uint32_t a1 = h2pack(s[2 * kk][2],     s[2 * kk][3]);
            uint32_t a2 = h2pack(s[2 * kk + 1][0], s[2 * kk + 1][1]);
            uint32_t a3 = h2pack(s[2 * kk + 1][2], s[2 * kk + 1][3]);
            #pragma unroll
            for (int nt = 0; nt < 8; nt++) {
                const int n = nt * 8 + r;
                uint32_t b0 = Vp[(8 * kk + c) * VPST + n];
                uint32_t b1 = Vp[(8 * kk + c + 4) * VPST + n];
                mma_f16(o[nt][0], o[nt][1], o[nt][2], o[nt][3], a0, a1, a2, a3, b0, b1);
            }
        }
    }

    // epilogue: normalize and write fp16 att
    const float inv0 = 1.f / l0;
    const float inv1 = 1.f / l1;
    const size_t row0 = (size_t)(b * SEQ + q0 + m0 + r) * DMODEL + h * HD;
    const size_t row1 = row0 + (size_t)8 * DMODEL;
    #pragma unroll
    for (int nt = 0; nt < 8; nt++) {
        const int col = nt * 8 + 2 * c;
        *(__half2*)(out + row0 + col) = __floats2half2_rn(o[nt][0] * inv0, o[nt][1] * inv0);
        *(__half2*)(out + row1 + col) = __floats2half2_rn(o[nt][2] * inv1, o[nt][3] * inv1);
    }
}

// ---------------------------------------------------------------------------
extern "C" void kernel_launch(void* const* d_in, const int* in_sizes, int n_in,
                              void* d_out, int out_size)
{
    const float* x     = (const float*)d_in[0];
    const float* w_qkv = (const float*)d_in[1];
    const float* w_out = (const float*)d_in[2];
    const float* b_out = (const float*)d_in[3];
    float* out = (float*)d_out;

    __half *qkvh, *xh, *wqh, *woh, *ath;
    cudaGetSymbolAddress((void**)&qkvh, g_qkvh);
    cudaGetSymbolAddress((void**)&xh,  g_xh);
    cudaGetSymbolAddress((void**)&wqh, g_wqh);
    cudaGetSymbolAddress((void**)&woh, g_woh);
    cudaGetSymbolAddress((void**)&ath, g_ath);

    // 0) prep: x -> fp16; weights -> transposed fp16 [N][K]
    {
        int n4 = ROWS * DMODEL / 4;
        cvt_f16_kernel<<<(n4 + 255) / 256, 256>>>(x, xh, n4);
        cvt_tr_f16_kernel<<<dim3(QKV_N / 32, DMODEL / 32), dim3(32, 8)>>>(w_qkv, wqh, DMODEL, QKV_N);
        cvt_tr_f16_kernel<<<dim3(DMODEL / 32, DMODEL / 32), dim3(32, 8)>>>(w_out, woh, DMODEL, DMODEL);
    }

    cudaFuncSetAttribute(f16_gemm_kernel,
                         cudaFuncAttributeMaxDynamicSharedMemorySize, GEMM_SMEM);

    // 1) QKV projection -> fp16 qkv directly
    {
        dim3 grid(QKV_N / 128, ROWS / 128);
        f16_gemm_kernel<<<grid, 256, GEMM_SMEM>>>(xh, wqh, nullptr, nullptr, qkvh,
                                                  ROWS, QKV_N, DMODEL);
    }

    // 2) Flash attention v7 (fp16 qkv: cp.async Q/K, PRMT V)
    {
        cudaFuncSetAttribute(flash_tc_kernel,
                             cudaFuncAttributeMaxDynamicSharedMemorySize, FLASH_SMEM);
        dim3 grid(SEQ / FBM, BATCH * NHEADS);
        flash_tc_kernel<<<grid, 256, FLASH_SMEM>>>(qkvh, ath);
    }

    // 3) Output projection + bias -> fp32 out
    {
        dim3 grid(DMODEL / 128, ROWS / 128);
        f16_gemm_kernel<<<grid, 256, GEMM_SMEM>>>(ath, woh, b_out, out, nullptr,
                                                  ROWS, DMODEL, DMODEL);
    }
}

// round 16
// speedup vs baseline: 2.2222x; 1.0006x over previous
#include <cuda_runtime.h>
#include <cuda_bf16.h>
#include <cuda_fp16.h>
#include <cstdint>

// Problem constants
#define BATCH 4
#define SEQ   2048
#define DMODEL 1024
#define NHEADS 16
#define HD    64
#define ROWS  (BATCH * SEQ)          // 8192
#define QKV_N (3 * DMODEL)           // 3072

// Scratch (allocation-free rule: __device__ globals)
__device__ __half g_qkvh[(size_t)ROWS * QKV_N];       // qkv as fp16
__device__ __half g_xh[(size_t)ROWS * DMODEL];        // x as fp16 [M][K]
__device__ __half g_wqh[(size_t)QKV_N * DMODEL];      // w_qkv^T fp16 [N][K]
__device__ __half g_woh[(size_t)DMODEL * DMODEL];     // w_out^T fp16 [N][K]
__device__ __half g_ath[(size_t)ROWS * DMODEL];       // att as fp16 [M][K]

// ---------------------------------------------------------------------------
// helpers
// ---------------------------------------------------------------------------
__device__ __forceinline__ uint32_t s2u(const void* p) {
    uint32_t a;
    asm("{ .reg .u64 t; cvta.to.shared.u64 t, %1; cvt.u32.u64 %0, t; }"
        : "=r"(a) : "l"(p));
    return a;
}
__device__ __forceinline__ void mma_f16(float& d0, float& d1, float& d2, float& d3,
                                        uint32_t a0, uint32_t a1, uint32_t a2, uint32_t a3,
                                        uint32_t b0, uint32_t b1)
{
    asm volatile(
        "mma.sync.aligned.m16n8k16.row.col.f32.f16.f16.f32 "
        "{%0,%1,%2,%3}, {%4,%5,%6,%7}, {%8,%9}, {%0,%1,%2,%3};"
        : "+f"(d0), "+f"(d1), "+f"(d2), "+f"(d3)
        : "r"(a0), "r"(a1), "r"(a2), "r"(a3), "r"(b0), "r"(b1));
}
__device__ __forceinline__ void ldmx4(uint32_t* r, uint32_t addr) {
    asm volatile("ldmatrix.sync.aligned.m8n8.x4.shared.b16 {%0,%1,%2,%3}, [%4];"
                 : "=r"(r[0]), "=r"(r[1]), "=r"(r[2]), "=r"(r[3]) : "r"(addr));
}
__device__ __forceinline__ void cpasync16(uint32_t dst, const void* src) {
    asm volatile("cp.async.cg.shared.global [%0], [%1], 16;" :: "r"(dst), "l"(src));
}
#define CP_COMMIT() asm volatile("cp.async.commit_group;" ::: "memory")
#define CP_WAIT0()  asm volatile("cp.async.wait_group 0;" ::: "memory")
#define CP_WAIT1()  asm volatile("cp.async.wait_group 1;" ::: "memory")

__device__ __forceinline__ uint32_t h2pack(float a, float b) {
    __half2 h = __floats2half2_rn(a, b);
    return *reinterpret_cast<uint32_t*>(&h);
}
// byte-mix two f16x2: (a.lo, b.lo) and (a.hi, b.hi)
__device__ __forceinline__ uint32_t prmt_lo(uint32_t a, uint32_t b) {
    uint32_t d; asm("prmt.b32 %0, %1, %2, 0x5410;" : "=r"(d) : "r"(a), "r"(b)); return d;
}
__device__ __forceinline__ uint32_t prmt_hi(uint32_t a, uint32_t b) {
    uint32_t d; asm("prmt.b32 %0, %1, %2, 0x7632;" : "=r"(d) : "r"(a), "r"(b)); return d;
}

// ---------------------------------------------------------------------------
// prep kernels: fp32 -> fp16 (plain and transposed)
// ---------------------------------------------------------------------------
__global__ void cvt_f16_kernel(const float* __restrict__ in,
                               __half* __restrict__ out, int n4)
{
    int i = blockIdx.x * blockDim.x + threadIdx.x;
    if (i >= n4) return;
    float4 v = *(const float4*)(in + (size_t)i * 4);
    *(__half2*)(out + (size_t)i * 4)     = __floats2half2_rn(v.x, v.y);
    *(__half2*)(out + (size_t)i * 4 + 2) = __floats2half2_rn(v.z, v.w);
}

// in[K][N] fp32 -> out[N][K] fp16
__global__ void cvt_tr_f16_kernel(const float* __restrict__ in,
                                  __half* __restrict__ out, int K, int N)
{
    __shared__ float t[32][33];
    const int n0 = blockIdx.x * 32, k0 = blockIdx.y * 32;
    const int tx = threadIdx.x, ty = threadIdx.y;
    #pragma unroll
    for (int r = 0; r < 4; r++)
        t[ty + 8 * r][tx] = in[(size_t)(k0 + ty + 8 * r) * N + n0 + tx];
    __syncthreads();
    #pragma unroll
    for (int r = 0; r < 4; r++)
        out[(size_t)(n0 + ty + 8 * r) * K + k0 + tx] = __float2half_rn(t[tx][ty + 8 * r]);
}

// ---------------------------------------------------------------------------
// FP16 GEMM v3: 3-stage cp.async pipeline, ONE __syncthreads per k32 chunk.
// Loads at iter i target buf (i+2)%3 (= last computed in iter i-1, protected
// by the top-of-iteration barrier). Same instruction values as round 14.
// ---------------------------------------------------------------------------
#define RST   40
#define ARR_B (128 * RST * 2)
#define STG_B (2 * ARR_B)                // 20480 B per stage
#define GEMM_SMEM (3 * STG_B)            // 61440 B

__global__ void __launch_bounds__(256, 2) f16_gemm_kernel(
    const __half* __restrict__ A, const __half* __restrict__ Bt,
    const float* __restrict__ bias,
    float* __restrict__ Cf, __half* __restrict__ Ch,
    int M, int N, int K)
{
    extern __shared__ char smem2[];
    const uint32_t sb = s2u(smem2);

    const int tid  = threadIdx.x;
    const int lane = tid & 31;
    const int warp = tid >> 5;
    const int m0 = blockIdx.y * 128;
    const int n0 = blockIdx.x * 128;

    const int wrow = warp >> 2;
    const int wcol = warp & 3;
    const int mbase = wrow * 64;
    const int nbase = wcol * 32;
    const int r = lane >> 2;
    const int c = lane & 3;
    const int lr = lane & 15;
    const int lc = lane >> 4;

    const __half* srcs[2] = { A + (size_t)m0 * K, Bt + (size_t)n0 * K };

    float acc[4][4][4];
    #pragma unroll
    for (int i = 0; i < 4; i++)
        #pragma unroll
        for (int j = 0; j < 4; j++)
            #pragma unroll
            for (int t = 0; t < 4; t++) acc[i][j][t] = 0.f;

    auto load_chunk = [&](int kc, int buf) {
        const uint32_t bb = sb + buf * STG_B;
        #pragma unroll
        for (int u = 0; u < 4; u++) {
            const int arr = u >> 1;
            const int w = (u & 1) * 256 + tid;
            const int row = w >> 2, j = w & 3;
            cpasync16(bb + arr * ARR_B + row * (RST * 2) + j * 16,
                      srcs[arr] + (size_t)row * K + kc * 32 + j * 8);
        }
        CP_COMMIT();
    };

    const int NCH = K / 32;              // 32 (K=1024)
    load_chunk(0, 0);
    load_chunk(1, 1);

    int buf = 0;
    for (int i = 0; i < NCH; i++) {
        if (i + 1 < NCH) { CP_WAIT1(); } else { CP_WAIT0(); }
        __syncthreads();   // chunk i landed AND all warps finished iter i-1

        // issue loads for chunk i+2 into buf (i+2)%3 (free: computed in i-1)
        if (i + 2 < NCH) {
            int nb = buf + 2; if (nb >= 3) nb -= 3;
            load_chunk(i + 2, nb);
        }

        const uint32_t baseA = sb + buf * STG_B;
        const uint32_t baseB = baseA + ARR_B;

        #pragma unroll
        for (int ks = 0; ks < 2; ks++) {
            const uint32_t ko = ks * 32;
            uint32_t ah[4][4], bh[2][4];
            #pragma unroll
            for (int mt = 0; mt < 4; mt++) {
                const uint32_t ro = (uint32_t)(mbase + mt * 16 + lr) * (RST * 2) + ko + lc * 16;
                ldmx4(ah[mt], baseA + ro);
            }
            #pragma unroll
            for (int p = 0; p < 2; p++) {
                const uint32_t ro = (uint32_t)(nbase + p * 16 + lr) * (RST * 2) + ko + lc * 16;
                ldmx4(bh[p], baseB + ro);
            }
            #pragma unroll
            for (int mt = 0; mt < 4; mt++)
                #pragma unroll
                for (int nt = 0; nt < 4; nt++) {
                    const int p = nt >> 1, q = nt & 1;
                    mma_f16(acc[mt][nt][0], acc[mt][nt][1], acc[mt][nt][2], acc[mt][nt][3],
                            ah[mt][0], ah[mt][1], ah[mt][2], ah[mt][3],
                            bh[p][q], bh[p][q + 2]);
                }
        }
        if (++buf == 3) buf = 0;
    }

    #pragma unroll
    for (int mt = 0; mt < 4; mt++) {
        const int row0 = m0 + mbase + mt * 16 + r;
        #pragma unroll
        for (int nt = 0; nt < 4; nt++) {
            const int col = n0 + nbase + nt * 8 + 2 * c;
            float2 v0 = make_float2(acc[mt][nt][0], acc[mt][nt][1]);
            float2 v1 = make_float2(acc[mt][nt][2], acc[mt][nt][3]);
            if (bias) {
                float2 bb = *(const float2*)(bias + col);
                v0.x += bb.x; v0.y += bb.y;
                v1.x += bb.x; v1.y += bb.y;
            }
            if (Ch) {
                *(__half2*)(Ch + (size_t)row0 * N + col)       = __floats2half2_rn(v0.x, v0.y);
                *(__half2*)(Ch + (size_t)(row0 + 8) * N + col) = __floats2half2_rn(v1.x, v1.y);
            } else {
                *(float2*)(Cf + (size_t)row0 * N + col)       = v0;
                *(float2*)(Cf + (size_t)(row0 + 8) * N + col) = v1;
            }
        }
    }
}

// ---------------------------------------------------------------------------
// Flash attention v7 (round-15 winner, byte-identical): fp16 single mma,
// zero-shuffle PV, cp.async Q/K, PRMT V. smem 36864 B -> 2 CTAs/SM.
// ---------------------------------------------------------------------------
#define FBM 128
#define FBN 64
#define QPST 36
#define KPST 36
#define VPST 72
#define FLASH_SMEM ((FBM*QPST + FBN*KPST + 32*VPST) * 4)   // 36864 B

__global__ void __launch_bounds__(256, 2) flash_tc_kernel(
    const __half* __restrict__ qkvh, __half* __restrict__ out)
{
    extern __shared__ uint32_t smf[];
    uint32_t* Qp = smf;
    uint32_t* Kp = Qp + FBM * QPST;
    uint32_t* Vp = Kp + FBN * KPST;

    const int tid  = threadIdx.x;
    const int lane = tid & 31;
    const int warp = tid >> 5;
    const int qt = (int)gridDim.x - 1 - (int)blockIdx.x;
    const int bh = blockIdx.y;
    const int b  = bh >> 4;
    const int h  = bh & 15;

    const size_t rs = (size_t)QKV_N;
    const __half* qb = qkvh + (size_t)b * SEQ * rs + h * HD;
    const __half* kb = qb + DMODEL;
    const __half* vb = qb + 2 * DMODEL;
    const int q0 = qt * FBM;

    for (int idx = tid; idx < FBM * 8; idx += 256) {
        const int row = idx >> 3, j4 = (idx & 7) * 4;
        cpasync16(s2u(&Qp[row * QPST + j4]),
                  qb + (size_t)(q0 + row) * rs + 8 * (idx & 7));
    }
    CP_COMMIT();

    const int r = lane >> 2;
    const int c = lane & 3;
    const int m0 = warp * 16;

    float o[8][4];
    #pragma unroll
    for (int nt = 0; nt < 8; nt++)
        #pragma unroll
        for (int t = 0; t < 4; t++) o[nt][t] = 0.f;
    float mx0 = -1e30f, mx1 = -1e30f, l0 = 0.f, l1 = 0.f;
    const float sl2e = 0.125f * 1.4426950408889634f;

    const int nkt = 2 * qt + 2;
    for (int kt = 0; kt < nkt; kt++) {
        __syncthreads();

        for (int idx = tid; idx < FBN * 8; idx += 256) {
            const int row = idx >> 3, j4 = (idx & 7) * 4;
            cpasync16(s2u(&Kp[row * KPST + j4]),
                      kb + (size_t)(kt * FBN + row) * rs + 8 * (idx & 7));
        }
        CP_COMMIT();

        for (int idx = tid; idx < 32 * 16; idx += 256) {
            const int k2 = idx >> 4, q4 = (idx & 15) * 4;
            const uint32_t* rowA = (const uint32_t*)(vb + (size_t)(kt * FBN + 2 * k2) * rs) + (q4 >> 1);
            const uint32_t* rowD = (const uint32_t*)((const __half*)rowA + rs);
            uint2 A = *(const uint2*)rowA;
            uint2 D = *(const uint2*)rowD;
            Vp[k2 * VPST + q4 + 0] = prmt_lo(A.x, D.x);
            Vp[k2 * VPST + q4 + 1] = prmt_hi(A.x, D.x);
            Vp[k2 * VPST + q4 + 2] = prmt_lo(A.y, D.y);
            Vp[k2 * VPST + q4 + 3] = prmt_hi(A.y, D.y);
        }
        CP_WAIT0();
        __syncthreads();

        float s[8][4];
        #pragma unroll
        for (int nt = 0; nt < 8; nt++)
            #pragma unroll
            for (int t = 0; t < 4; t++) s[nt][t] = 0.f;

        #pragma unroll
        for (int g = 0; g < 4; g++) {
            const int qo = 8 * g + c;
            uint32_t a0 = Qp[(m0 + r) * QPST + qo];
            uint32_t a1 = Qp[(m0 + r + 8) * QPST + qo];
            uint32_t a2 = Qp[(m0 + r) * QPST + qo + 4];
            uint32_t a3 = Qp[(m0 + r + 8) * QPST + qo + 4];
            #pragma unroll
            for (int nt = 0; nt < 8; nt++) {
                const int n = nt * 8 + r;
                uint32_t b0 = Kp[n * KPST + qo];
                uint32_t b1 = Kp[n * KPST + qo + 4];
                mma_f16(s[nt][0], s[nt][1], s[nt][2], s[nt][3], a0, a1, a2, a3, b0, b1);
            }
        }

        if (kt >= 2 * qt) {
            const int q0i = q0 + m0 + r;
            #pragma unroll
            for (int nt = 0; nt < 8; nt++) {
                int k0i = kt * FBN + nt * 8 + 2 * c;
                if (k0i     > q0i)     s[nt][0] = -1e30f;
                if (k0i + 1 > q0i)     s[nt][1] = -1e30f;
                if (k0i     > q0i + 8) s[nt][2] = -1e30f;
                if (k0i + 1 > q0i + 8) s[nt][3] = -1e30f;
            }
        }

        {
            float t = -1e30f;
            #pragma unroll
            for (int nt = 0; nt < 8; nt++) t = fmaxf(t, fmaxf(s[nt][0], s[nt][1]));
            t = fmaxf(t, __shfl_xor_sync(0xffffffffu, t, 1));
            t = fmaxf(t, __shfl_xor_sync(0xffffffffu, t, 2));
            t *= sl2e;
            float mn = fmaxf(mx0, t);
            float alpha = exp2f(mx0 - mn);
            float ps = 0.f;
            #pragma unroll
            for (int nt = 0; nt < 8; nt++) {
                float p0 = exp2f(s[nt][0] * sl2e - mn);
                float p1 = exp2f(s[nt][1] * sl2e - mn);
                s[nt][0] = p0; s[nt][1] = p1; ps += p0 + p1;
            }
            ps += __shfl_xor_sync(0xffffffffu, ps, 1);
            ps += __shfl_xor_sync(0xffffffffu, ps, 2);
            l0 = l0 * alpha + ps; mx0 = mn;
            #pragma unroll
            for (int nt = 0; nt < 8; nt++) { o[nt][0] *= alpha; o[nt][1] *= alpha; }
        }
        {
            float t = -1e30f;
            #pragma unroll
            for (int nt = 0; nt < 8; nt++) t = fmaxf(t, fmaxf(s[nt][2], s[nt][3]));
            t = fmaxf(t, __shfl_xor_sync(0xffffffffu, t, 1));
            t = fmaxf(t, __shfl_xor_sync(0xffffffffu, t, 2));
            t *= sl2e;
            float mn = fmaxf(mx1, t);
            float alpha = exp2f(mx1 - mn);
            float ps = 0.f;
            #pragma unroll
            for (int nt = 0; nt < 8; nt++) {
                float p0 = exp2f(s[nt][2] * sl2e - mn);
                float p1 = exp2f(s[nt][3] * sl2e - mn);
                s[nt][2] = p0; s[nt][3] = p1; ps += p0 + p1;
            }
            ps += __shfl_xor_sync(0xffffffffu, ps, 1);
            ps += __shfl_xor_sync(0xffffffffu, ps, 2);
            l1 = l1 * alpha + ps; mx1 = mn;
            #pragma unroll
            for (int nt = 0; nt < 8; nt++) { o[nt][2] *= alpha; o[nt][3] *= alpha; }
        }

        #pragma unroll
        for (int kk = 0; kk < 4; kk++) {
            uint32_t a0 = h2pack(s[2 * kk][0],     s[2 * kk][1]);
            uint32_t a1 = h2pack(s[2 * kk][2],     s[2 * kk][3]);
            uint32_t a2 = h2pack(s[2 * kk + 1][0], s[2 * kk + 1][1]);
            uint32_t a3 = h2pack(s[2 * kk + 1][2], s[2 * kk + 1][3]);
            #pragma unroll
            for (int nt = 0; nt < 8; nt++) {
                const int n = nt * 8 + r;
                uint32_t b0 = Vp[(8 * kk + c) * VPST + n];
                uint32_t b1 = Vp[(8 * kk + c + 4) * VPST + n];
                mma_f16(o[nt][0], o[nt][1], o[nt][2], o[nt][3], a0, a1, a2, a3, b0, b1);
            }
        }
    }

    const float inv0 = 1.f / l0;
    const float inv1 = 1.f / l1;
    const size_t row0 = (size_t)(b * SEQ + q0 + m0 + r) * DMODEL + h * HD;
    const size_t row1 = row0 + (size_t)8 * DMODEL;
    #pragma unroll
    for (int nt = 0; nt < 8; nt++) {
        const int col = nt * 8 + 2 * c;
        *(__half2*)(out + row0 + col) = __floats2half2_rn(o[nt][0] * inv0, o[nt][1] * inv0);
        *(__half2*)(out + row1 + col) = __floats2half2_rn(o[nt][2] * inv1, o[nt][3] * inv1);
    }
}

// ---------------------------------------------------------------------------
extern "C" void kernel_launch(void* const* d_in, const int* in_sizes, int n_in,
                              void* d_out, int out_size)
{
    const float* x     = (const float*)d_in[0];
    const float* w_qkv = (const float*)d_in[1];
    const float* w_out = (const float*)d_in[2];
    const float* b_out = (const float*)d_in[3];
    float* out = (float*)d_out;

    __half *qkvh, *xh, *wqh, *woh, *ath;
    cudaGetSymbolAddress((void**)&qkvh, g_qkvh);
    cudaGetSymbolAddress((void**)&xh,  g_xh);
    cudaGetSymbolAddress((void**)&wqh, g_wqh);
    cudaGetSymbolAddress((void**)&woh, g_woh);
    cudaGetSymbolAddress((void**)&ath, g_ath);

    // 0) prep: x -> fp16; weights -> transposed fp16 [N][K]
    {
        int n4 = ROWS * DMODEL / 4;
        cvt_f16_kernel<<<(n4 + 255) / 256, 256>>>(x, xh, n4);
        cvt_tr_f16_kernel<<<dim3(QKV_N / 32, DMODEL / 32), dim3(32, 8)>>>(w_qkv, wqh, DMODEL, QKV_N);
        cvt_tr_f16_kernel<<<dim3(DMODEL / 32, DMODEL / 32), dim3(32, 8)>>>(w_out, woh, DMODEL, DMODEL);
    }

    cudaFuncSetAttribute(f16_gemm_kernel,
                         cudaFuncAttributeMaxDynamicSharedMemorySize, GEMM_SMEM);

    // 1) QKV projection -> fp16 qkv directly (3-stage pipeline)
    {
        dim3 grid(QKV_N / 128, ROWS / 128);
        f16_gemm_kernel<<<grid, 256, GEMM_SMEM>>>(xh, wqh, nullptr, nullptr, qkvh,
                                                  ROWS, QKV_N, DMODEL);
    }

    // 2) Flash attention v7 (fp16 qkv: cp.async Q/K, PRMT V)
    {
        cudaFuncSetAttribute(flash_tc_kernel,
                             cudaFuncAttributeMaxDynamicSharedMemorySize, FLASH_SMEM);
        dim3 grid(SEQ / FBM, BATCH * NHEADS);
        flash_tc_kernel<<<grid, 256, FLASH_SMEM>>>(qkvh, ath);
    }

    // 3) Output projection + bias -> fp32 out
    {
        dim3 grid(DMODEL / 128, ROWS / 128);
        f16_gemm_kernel<<<grid, 256, GEMM_SMEM>>>(ath, woh, b_out, out, nullptr,
                                                  ROWS, DMODEL, DMODEL);
    }
}

// round 17
// speedup vs baseline: 2.4276x; 1.0924x over previous
#include <cuda_runtime.h>
#include <cuda_bf16.h>
#include <cuda_fp16.h>
#include <cstdint>

// Problem constants
#define BATCH 4
#define SEQ   2048
#define DMODEL 1024
#define NHEADS 16
#define HD    64
#define ROWS  (BATCH * SEQ)          // 8192
#define QKV_N (3 * DMODEL)           // 3072

// Scratch (allocation-free rule: __device__ globals)
__device__ __half g_qkvh[(size_t)ROWS * QKV_N];       // qkv as fp16
__device__ __half g_xh[(size_t)ROWS * DMODEL];        // x as fp16 [M][K]
__device__ __half g_wqh[(size_t)QKV_N * DMODEL];      // w_qkv^T fp16 [N][K]
__device__ __half g_woh[(size_t)DMODEL * DMODEL];     // w_out^T fp16 [N][K]
__device__ __half g_ath[(size_t)ROWS * DMODEL];       // att as fp16 [M][K]

// ---------------------------------------------------------------------------
// helpers
// ---------------------------------------------------------------------------
__device__ __forceinline__ uint32_t s2u(const void* p) {
    uint32_t a;
    asm("{ .reg .u64 t; cvta.to.shared.u64 t, %1; cvt.u32.u64 %0, t; }"
        : "=r"(a) : "l"(p));
    return a;
}
__device__ __forceinline__ void mma_f16(float& d0, float& d1, float& d2, float& d3,
                                        uint32_t a0, uint32_t a1, uint32_t a2, uint32_t a3,
                                        uint32_t b0, uint32_t b1)
{
    asm volatile(
        "mma.sync.aligned.m16n8k16.row.col.f32.f16.f16.f32 "
        "{%0,%1,%2,%3}, {%4,%5,%6,%7}, {%8,%9}, {%0,%1,%2,%3};"
        : "+f"(d0), "+f"(d1), "+f"(d2), "+f"(d3)
        : "r"(a0), "r"(a1), "r"(a2), "r"(a3), "r"(b0), "r"(b1));
}
__device__ __forceinline__ void ldmx4(uint32_t* r, uint32_t addr) {
    asm volatile("ldmatrix.sync.aligned.m8n8.x4.shared.b16 {%0,%1,%2,%3}, [%4];"
                 : "=r"(r[0]), "=r"(r[1]), "=r"(r[2]), "=r"(r[3]) : "r"(addr));
}
__device__ __forceinline__ void cpasync16(uint32_t dst, const void* src) {
    asm volatile("cp.async.cg.shared.global [%0], [%1], 16;" :: "r"(dst), "l"(src));
}
#define CP_COMMIT() asm volatile("cp.async.commit_group;" ::: "memory")
#define CP_WAIT0()  asm volatile("cp.async.wait_group 0;" ::: "memory")
#define CP_WAIT1()  asm volatile("cp.async.wait_group 1;" ::: "memory")

__device__ __forceinline__ uint32_t h2pack(float a, float b) {
    __half2 h = __floats2half2_rn(a, b);
    return *reinterpret_cast<uint32_t*>(&h);
}
// byte-mix two f16x2: (a.lo, b.lo) and (a.hi, b.hi)
__device__ __forceinline__ uint32_t prmt_lo(uint32_t a, uint32_t b) {
    uint32_t d; asm("prmt.b32 %0, %1, %2, 0x5410;" : "=r"(d) : "r"(a), "r"(b)); return d;
}
__device__ __forceinline__ uint32_t prmt_hi(uint32_t a, uint32_t b) {
    uint32_t d; asm("prmt.b32 %0, %1, %2, 0x7632;" : "=r"(d) : "r"(a), "r"(b)); return d;
}

// ---------------------------------------------------------------------------
// prep kernels: fp32 -> fp16 (plain and transposed)
// ---------------------------------------------------------------------------
__global__ void cvt_f16_kernel(const float* __restrict__ in,
                               __half* __restrict__ out, int n4)
{
    int i = blockIdx.x * blockDim.x + threadIdx.x;
    if (i >= n4) return;
    float4 v = *(const float4*)(in + (size_t)i * 4);
    *(__half2*)(out + (size_t)i * 4)     = __floats2half2_rn(v.x, v.y);
    *(__half2*)(out + (size_t)i * 4 + 2) = __floats2half2_rn(v.z, v.w);
}

// in[K][N] fp32 -> out[N][K] fp16
__global__ void cvt_tr_f16_kernel(const float* __restrict__ in,
                                  __half* __restrict__ out, int K, int N)
{
    __shared__ float t[32][33];
    const int n0 = blockIdx.x * 32, k0 = blockIdx.y * 32;
    const int tx = threadIdx.x, ty = threadIdx.y;
    #pragma unroll
    for (int r = 0; r < 4; r++)
        t[ty + 8 * r][tx] = in[(size_t)(k0 + ty + 8 * r) * N + n0 + tx];
    __syncthreads();
    #pragma unroll
    for (int r = 0; r < 4; r++)
        out[(size_t)(n0 + ty + 8 * r) * K + k0 + tx] = __float2half_rn(t[tx][ty + 8 * r]);
}

// ---------------------------------------------------------------------------
// FP16 GEMM v4: K-chunk 64 (4 k16 steps = 64 mmas per barrier period, 2x the
// mma density of v2/v3), 2-stage cp.async pipeline, ldmatrix.x4 fragments.
// Row stride 72 halves (144 B): ldmatrix banks step 36 = 4 mod 32 -> the 8
// rows hit banks {0,4,...,28}, conflict-free. Numerics identical to v2/v3.
// ---------------------------------------------------------------------------
#define RST   72                          // halves per row (64 data + 8 pad)
#define ARR_B (128 * RST * 2)             // 18432 B per array
#define STG_B (2 * ARR_B)                 // 36864 B per stage (A|B)
#define GEMM_SMEM (2 * STG_B)             // 73728 B

__global__ void __launch_bounds__(256, 2) f16_gemm_kernel(
    const __half* __restrict__ A, const __half* __restrict__ Bt,
    const float* __restrict__ bias,
    float* __restrict__ Cf, __half* __restrict__ Ch,
    int M, int N, int K)
{
    extern __shared__ char smem2[];
    const uint32_t sb = s2u(smem2);

    const int tid  = threadIdx.x;
    const int lane = tid & 31;
    const int warp = tid >> 5;
    const int m0 = blockIdx.y * 128;
    const int n0 = blockIdx.x * 128;

    const int wrow = warp >> 2;
    const int wcol = warp & 3;
    const int mbase = wrow * 64;
    const int nbase = wcol * 32;
    const int r = lane >> 2;
    const int c = lane & 3;
    const int lr = lane & 15;
    const int lc = lane >> 4;

    const __half* srcs[2] = { A + (size_t)m0 * K, Bt + (size_t)n0 * K };

    float acc[4][4][4];
    #pragma unroll
    for (int i = 0; i < 4; i++)
        #pragma unroll
        for (int j = 0; j < 4; j++)
            #pragma unroll
            for (int t = 0; t < 4; t++) acc[i][j][t] = 0.f;

    // one chunk = 64 k-cols of both arrays. 8 cp.async per thread.
    auto load_chunk = [&](int kc, int buf) {
        const uint32_t bb = sb + buf * STG_B;
        #pragma unroll
        for (int u = 0; u < 8; u++) {
            const int arr = u >> 2;
            const int w = (u & 3) * 256 + tid;      // 0..1023
            const int row = w >> 3, j = w & 7;
            cpasync16(bb + arr * ARR_B + row * (RST * 2) + j * 16,
                      srcs[arr] + (size_t)row * K + kc * 64 + j * 8);
        }
        CP_COMMIT();
    };

    const int NCH = K / 64;               // 16 (K=1024)
    load_chunk(0, 0);
    load_chunk(1, 1);

    for (int i = 0; i < NCH; i++) {
        const int buf = i & 1;
        if (i + 1 < NCH) { CP_WAIT1(); } else { CP_WAIT0(); }
        __syncthreads();

        const uint32_t baseA = sb + buf * STG_B;
        const uint32_t baseB = baseA + ARR_B;

        #pragma unroll
        for (int ks = 0; ks < 4; ks++) {
            const uint32_t ko = ks * 32;    // k16 = 16 halves = 32 B
            uint32_t ah[4][4], bh[2][4];
            #pragma unroll
            for (int mt = 0; mt < 4; mt++) {
                const uint32_t ro = (uint32_t)(mbase + mt * 16 + lr) * (RST * 2) + ko + lc * 16;
                ldmx4(ah[mt], baseA + ro);
            }
            #pragma unroll
            for (int p = 0; p < 2; p++) {
                const uint32_t ro = (uint32_t)(nbase + p * 16 + lr) * (RST * 2) + ko + lc * 16;
                ldmx4(bh[p], baseB + ro);
            }
            #pragma unroll
            for (int mt = 0; mt < 4; mt++)
                #pragma unroll
                for (int nt = 0; nt < 4; nt++) {
                    const int p = nt >> 1, q = nt & 1;
                    mma_f16(acc[mt][nt][0], acc[mt][nt][1], acc[mt][nt][2], acc[mt][nt][3],
                            ah[mt][0], ah[mt][1], ah[mt][2], ah[mt][3],
                            bh[p][q], bh[p][q + 2]);
                }
        }
        __syncthreads();
        if (i + 2 < NCH) load_chunk(i + 2, buf);
    }

    #pragma unroll
    for (int mt = 0; mt < 4; mt++) {
        const int row0 = m0 + mbase + mt * 16 + r;
        #pragma unroll
        for (int nt = 0; nt < 4; nt++) {
            const int col = n0 + nbase + nt * 8 + 2 * c;
            float2 v0 = make_float2(acc[mt][nt][0], acc[mt][nt][1]);
            float2 v1 = make_float2(acc[mt][nt][2], acc[mt][nt][3]);
            if (bias) {
                float2 bb = *(const float2*)(bias + col);
                v0.x += bb.x; v0.y += bb.y;
                v1.x += bb.x; v1.y += bb.y;
            }
            if (Ch) {
                *(__half2*)(Ch + (size_t)row0 * N + col)       = __floats2half2_rn(v0.x, v0.y);
                *(__half2*)(Ch + (size_t)(row0 + 8) * N + col) = __floats2half2_rn(v1.x, v1.y);
            } else {
                *(float2*)(Cf + (size_t)row0 * N + col)       = v0;
                *(float2*)(Cf + (size_t)(row0 + 8) * N + col) = v1;
            }
        }
    }
}

// ---------------------------------------------------------------------------
// Flash attention v7 (round-15 winner, byte-identical): fp16 single mma,
// zero-shuffle PV, cp.async Q/K, PRMT V. smem 36864 B -> 2 CTAs/SM.
// ---------------------------------------------------------------------------
#define FBM 128
#define FBN 64
#define QPST 36
#define KPST 36
#define VPST 72
#define FLASH_SMEM ((FBM*QPST + FBN*KPST + 32*VPST) * 4)   // 36864 B

__global__ void __launch_bounds__(256, 2) flash_tc_kernel(
    const __half* __restrict__ qkvh, __half* __restrict__ out)
{
    extern __shared__ uint32_t smf[];
    uint32_t* Qp = smf;
    uint32_t* Kp = Qp + FBM * QPST;
    uint32_t* Vp = Kp + FBN * KPST;

    const int tid  = threadIdx.x;
    const int lane = tid & 31;
    const int warp = tid >> 5;
    const int qt = (int)gridDim.x - 1 - (int)blockIdx.x;
    const int bh = blockIdx.y;
    const int b  = bh >> 4;
    const int h  = bh & 15;

    const size_t rs = (size_t)QKV_N;
    const __half* qb = qkvh + (size_t)b * SEQ * rs + h * HD;
    const __half* kb = qb + DMODEL;
    const __half* vb = qb + 2 * DMODEL;
    const int q0 = qt * FBM;

    for (int idx = tid; idx < FBM * 8; idx += 256) {
        const int row = idx >> 3, j4 = (idx & 7) * 4;
        cpasync16(s2u(&Qp[row * QPST + j4]),
                  qb + (size_t)(q0 + row) * rs + 8 * (idx & 7));
    }
    CP_COMMIT();

    const int r = lane >> 2;
    const int c = lane & 3;
    const int m0 = warp * 16;

    float o[8][4];
    #pragma unroll
    for (int nt = 0; nt < 8; nt++)
        #pragma unroll
        for (int t = 0; t < 4; t++) o[nt][t] = 0.f;
    float mx0 = -1e30f, mx1 = -1e30f, l0 = 0.f, l1 = 0.f;
    const float sl2e = 0.125f * 1.4426950408889634f;

    const int nkt = 2 * qt + 2;
    for (int kt = 0; kt < nkt; kt++) {
        __syncthreads();

        for (int idx = tid; idx < FBN * 8; idx += 256) {
            const int row = idx >> 3, j4 = (idx & 7) * 4;
            cpasync16(s2u(&Kp[row * KPST + j4]),
                      kb + (size_t)(kt * FBN + row) * rs + 8 * (idx & 7));
        }
        CP_COMMIT();

        for (int idx = tid; idx < 32 * 16; idx += 256) {
            const int k2 = idx >> 4, q4 = (idx & 15) * 4;
            const uint32_t* rowA = (const uint32_t*)(vb + (size_t)(kt * FBN + 2 * k2) * rs) + (q4 >> 1);
            const uint32_t* rowD = (const uint32_t*)((const __half*)rowA + rs);
            uint2 A = *(const uint2*)rowA;
            uint2 D = *(const uint2*)rowD;
            Vp[k2 * VPST + q4 + 0] = prmt_lo(A.x, D.x);
            Vp[k2 * VPST + q4 + 1] = prmt_hi(A.x, D.x);
            Vp[k2 * VPST + q4 + 2] = prmt_lo(A.y, D.y);
            Vp[k2 * VPST + q4 + 3] = prmt_hi(A.y, D.y);
        }
        CP_WAIT0();
        __syncthreads();

        float s[8][4];
        #pragma unroll
        for (int nt = 0; nt < 8; nt++)
            #pragma unroll
            for (int t = 0; t < 4; t++) s[nt][t] = 0.f;

        #pragma unroll
        for (int g = 0; g < 4; g++) {
            const int qo = 8 * g + c;
            uint32_t a0 = Qp[(m0 + r) * QPST + qo];
            uint32_t a1 = Qp[(m0 + r + 8) * QPST + qo];
            uint32_t a2 = Qp[(m0 + r) * QPST + qo + 4];
            uint32_t a3 = Qp[(m0 + r + 8) * QPST + qo + 4];
            #pragma unroll
            for (int nt = 0; nt < 8; nt++) {
                const int n = nt * 8 + r;
                uint32_t b0 = Kp[n * KPST + qo];
                uint32_t b1 = Kp[n * KPST + qo + 4];
                mma_f16(s[nt][0], s[nt][1], s[nt][2], s[nt][3], a0, a1, a2, a3, b0, b1);
            }
        }

        if (kt >= 2 * qt) {
            const int q0i = q0 + m0 + r;
            #pragma unroll
            for (int nt = 0; nt < 8; nt++) {
                int k0i = kt * FBN + nt * 8 + 2 * c;
                if (k0i     > q0i)     s[nt][0] = -1e30f;
                if (k0i + 1 > q0i)     s[nt][1] = -1e30f;
                if (k0i     > q0i + 8) s[nt][2] = -1e30f;
                if (k0i + 1 > q0i + 8) s[nt][3] = -1e30f;
            }
        }

        {
            float t = -1e30f;
            #pragma unroll
            for (int nt = 0; nt < 8; nt++) t = fmaxf(t, fmaxf(s[nt][0], s[nt][1]));
            t = fmaxf(t, __shfl_xor_sync(0xffffffffu, t, 1));
            t = fmaxf(t, __shfl_xor_sync(0xffffffffu, t, 2));
            t *= sl2e;
            float mn = fmaxf(mx0, t);
            float alpha = exp2f(mx0 - mn);
            float ps = 0.f;
            #pragma unroll
            for (int nt = 0; nt < 8; nt++) {
                float p0 = exp2f(s[nt][0] * sl2e - mn);
                float p1 = exp2f(s[nt][1] * sl2e - mn);
                s[nt][0] = p0; s[nt][1] = p1; ps += p0 + p1;
            }
            ps += __shfl_xor_sync(0xffffffffu, ps, 1);
            ps += __shfl_xor_sync(0xffffffffu, ps, 2);
            l0 = l0 * alpha + ps; mx0 = mn;
            #pragma unroll
            for (int nt = 0; nt < 8; nt++) { o[nt][0] *= alpha; o[nt][1] *= alpha; }
        }
        {
            float t = -1e30f;
            #pragma unroll
            for (int nt = 0; nt < 8; nt++) t = fmaxf(t, fmaxf(s[nt][2], s[nt][3]));
            t = fmaxf(t, __shfl_xor_sync(0xffffffffu, t, 1));
            t = fmaxf(t, __shfl_xor_sync(0xffffffffu, t, 2));
            t *= sl2e;
            float mn = fmaxf(mx1, t);
            float alpha = exp2f(mx1 - mn);
            float ps = 0.f;
            #pragma unroll
            for (int nt = 0; nt < 8; nt++) {
                float p0 = exp2f(s[nt][2] * sl2e - mn);
                float p1 = exp2f(s[nt][3] * sl2e - mn);
                s[nt][2] = p0; s[nt][3] = p1; ps += p0 + p1;
            }
            ps += __shfl_xor_sync(0xffffffffu, ps, 1);
            ps += __shfl_xor_sync(0xffffffffu, ps, 2);
            l1 = l1 * alpha + ps; mx1 = mn;
            #pragma unroll
            for (int nt = 0; nt < 8; nt++) { o[nt][2] *= alpha; o[nt][3] *= alpha; }
        }

        #pragma unroll
        for (int kk = 0; kk < 4; kk++) {
            uint32_t a0 = h2pack(s[2 * kk][0],     s[2 * kk][1]);
            uint32_t a1 = h2pack(s[2 * kk][2],     s[2 * kk][3]);
            uint32_t a2 = h2pack(s[2 * kk + 1][0], s[2 * kk + 1][1]);
            uint32_t a3 = h2pack(s[2 * kk + 1][2], s[2 * kk + 1][3]);
            #pragma unroll
            for (int nt = 0; nt < 8; nt++) {
                const int n = nt * 8 + r;
                uint32_t b0 = Vp[(8 * kk + c) * VPST + n];
                uint32_t b1 = Vp[(8 * kk + c + 4) * VPST + n];
                mma_f16(o[nt][0], o[nt][1], o[nt][2], o[nt][3], a0, a1, a2, a3, b0, b1);
            }
        }
    }

    const float inv0 = 1.f / l0;
    const float inv1 = 1.f / l1;
    const size_t row0 = (size_t)(b * SEQ + q0 + m0 + r) * DMODEL + h * HD;
    const size_t row1 = row0 + (size_t)8 * DMODEL;
    #pragma unroll
    for (int nt = 0; nt < 8; nt++) {
        const int col = nt * 8 + 2 * c;
        *(__half2*)(out + row0 + col) = __floats2half2_rn(o[nt][0] * inv0, o[nt][1] * inv0);
        *(__half2*)(out + row1 + col) = __floats2half2_rn(o[nt][2] * inv1, o[nt][3] * inv1);
    }
}

// ---------------------------------------------------------------------------
extern "C" void kernel_launch(void* const* d_in, const int* in_sizes, int n_in,
                              void* d_out, int out_size)
{
    const float* x     = (const float*)d_in[0];
    const float* w_qkv = (const float*)d_in[1];
    const float* w_out = (const float*)d_in[2];
    const float* b_out = (const float*)d_in[3];
    float* out = (float*)d_out;

    __half *qkvh, *xh, *wqh, *woh, *ath;
    cudaGetSymbolAddress((void**)&qkvh, g_qkvh);
    cudaGetSymbolAddress((void**)&xh,  g_xh);
    cudaGetSymbolAddress((void**)&wqh, g_wqh);
    cudaGetSymbolAddress((void**)&woh, g_woh);
    cudaGetSymbolAddress((void**)&ath, g_ath);

    // 0) prep: x -> fp16; weights -> transposed fp16 [N][K]
    {
        int n4 = ROWS * DMODEL / 4;
        cvt_f16_kernel<<<(n4 + 255) / 256, 256>>>(x, xh, n4);
        cvt_tr_f16_kernel<<<dim3(QKV_N / 32, DMODEL / 32), dim3(32, 8)>>>(w_qkv, wqh, DMODEL, QKV_N);
        cvt_tr_f16_kernel<<<dim3(DMODEL / 32, DMODEL / 32), dim3(32, 8)>>>(w_out, woh, DMODEL, DMODEL);
    }

    cudaFuncSetAttribute(f16_gemm_kernel,
                         cudaFuncAttributeMaxDynamicSharedMemorySize, GEMM_SMEM);

    // 1) QKV projection -> fp16 qkv directly (k64 chunks)
    {
        dim3 grid(QKV_N / 128, ROWS / 128);
        f16_gemm_kernel<<<grid, 256, GEMM_SMEM>>>(xh, wqh, nullptr, nullptr, qkvh,
                                                  ROWS, QKV_N, DMODEL);
    }

    // 2) Flash attention v7 (fp16 qkv: cp.async Q/K, PRMT V)
    {
        cudaFuncSetAttribute(flash_tc_kernel,
                             cudaFuncAttributeMaxDynamicSharedMemorySize, FLASH_SMEM);
        dim3 grid(SEQ / FBM, BATCH * NHEADS);
        flash_tc_kernel<<<grid, 256, FLASH_SMEM>>>(qkvh, ath);
    }

    // 3) Output projection + bias -> fp32 out
    {
        dim3 grid(DMODEL / 128, ROWS / 128);
        f16_gemm_kernel<<<grid, 256, GEMM_SMEM>>>(ath, woh, b_out, out, nullptr,
                                                  ROWS, DMODEL, DMODEL);
    }
}